// round 4
// baseline (speedup 1.0000x reference)
#include <cuda_runtime.h>
#include <cuda_fp16.h>
#include <cstdint>

#define NN 100000
#define EE 1600000
#define HH 128
#define GG 512
#define BN_EPS 1e-5f
#define SCAN_B 1024
#define NB ((NN + SCAN_B - 1) / SCAN_B)   // 98 scan blocks

// ---------------- scratch (device globals: no allocation allowed) -----------
__device__ __half g_t[(size_t)NN * HH];   // GEMM output t = h @ W' (fp16)
__device__ __half g_h[(size_t)NN * HH];   // activated hidden (fp16)
__device__ __half g_Wh[3 * HH * HH];      // BN-folded fp16 weights
__device__ float  g_beta[3 * HH];         // BN-folded shifts
__device__ float  g_dinv[NN];
__device__ int    g_deg[NN];
__device__ int    g_rowptr[NN + 1];
__device__ int    g_cursor[NN];
__device__ int    g_col[EE];
__device__ float  g_gsum[GG];
__device__ int    g_gcnt[GG];
__device__ int    g_part[NB];

__device__ __forceinline__ uint32_t s2u(const void* p) {
    return (uint32_t)__cvta_generic_to_shared(p);
}

// ---------------- preprocessing kernels ------------------------------------
__global__ void k_zero() {
    int i = blockIdx.x * blockDim.x + threadIdx.x;
    if (i < NN) g_deg[i] = 0;
    if (i < GG) { g_gsum[i] = 0.0f; g_gcnt[i] = 0; }
}

// degree histogram over dst + per-graph node counts (fused)
__global__ void k_hist(const int* __restrict__ ei, const int* __restrict__ batch) {
    int e = blockIdx.x * blockDim.x + threadIdx.x;
    if (e < EE) atomicAdd(&g_deg[ei[EE + e]], 1);
    if (e < NN) atomicAdd(&g_gcnt[batch[e]], 1);
}

__global__ void k_scan_local() {
    __shared__ int sh[SCAN_B];
    int tx = threadIdx.x;
    int i = blockIdx.x * SCAN_B + tx;
    int v = (i < NN) ? g_deg[i] : 0;
    if (i < NN) g_dinv[i] = rsqrtf((float)(v + 1));   // fused dinv (+1 self-loop)
    sh[tx] = v;
    __syncthreads();
    for (int off = 1; off < SCAN_B; off <<= 1) {
        int t = (tx >= off) ? sh[tx - off] : 0;
        __syncthreads();
        sh[tx] += t;
        __syncthreads();
    }
    if (i < NN) g_rowptr[i] = sh[tx] - v;        // exclusive
    if (tx == SCAN_B - 1) g_part[blockIdx.x] = sh[tx];
}

__global__ void k_scan_part() {
    __shared__ int sh[128];
    int tx = threadIdx.x;
    int v = (tx < NB) ? g_part[tx] : 0;
    sh[tx] = v;
    __syncthreads();
    for (int off = 1; off < 128; off <<= 1) {
        int t = (tx >= off) ? sh[tx - off] : 0;
        __syncthreads();
        sh[tx] += t;
        __syncthreads();
    }
    if (tx < NB) g_part[tx] = sh[tx] - v;        // exclusive block offsets
}

__global__ void k_scan_add() {
    int i = blockIdx.x * blockDim.x + threadIdx.x;
    if (i < NN) {
        int v = g_rowptr[i] + g_part[i >> 10];
        g_rowptr[i] = v;
        g_cursor[i] = v;
    }
    if (i == 0) g_rowptr[NN] = EE;
}

__global__ void k_fill(const int* __restrict__ ei) {
    int e = blockIdx.x * blockDim.x + threadIdx.x;
    if (e < EE) {
        int src = ei[e];
        int dst = ei[EE + e];
        int p = atomicAdd(&g_cursor[dst], 1);
        g_col[p] = src;
    }
}

// Fold BN scale into W columns (fp16) for all 3 layers, compute folded shifts.
__global__ void k_prep_w(const float* __restrict__ W1v, const float* __restrict__ W2v,
                         const float* __restrict__ W3v,
                         const float* __restrict__ b1v, const float* __restrict__ b2v,
                         const float* __restrict__ b3v,
                         const float* __restrict__ ga1, const float* __restrict__ ga2,
                         const float* __restrict__ ga3,
                         const float* __restrict__ be1, const float* __restrict__ be2,
                         const float* __restrict__ be3,
                         const float* __restrict__ m1v, const float* __restrict__ m2v,
                         const float* __restrict__ m3v,
                         const float* __restrict__ v1v, const float* __restrict__ v2v,
                         const float* __restrict__ v3v) {
    int layer = blockIdx.y;
    const float* W  = layer == 0 ? W1v : layer == 1 ? W2v : W3v;
    const float* b  = layer == 0 ? b1v : layer == 1 ? b2v : b3v;
    const float* ga = layer == 0 ? ga1 : layer == 1 ? ga2 : ga3;
    const float* be = layer == 0 ? be1 : layer == 1 ? be2 : be3;
    const float* m  = layer == 0 ? m1v : layer == 1 ? m2v : m3v;
    const float* v  = layer == 0 ? v1v : layer == 1 ? v2v : v3v;
    int idx = blockIdx.x * blockDim.x + threadIdx.x;
    if (idx < HH * HH) {
        int n = idx & (HH - 1);
        float alpha = ga[n] * rsqrtf(v[n] + BN_EPS);
        g_Wh[layer * HH * HH + idx] = __float2half(W[idx] * alpha);
    }
    if (idx < HH) {
        float alpha = ga[idx] * rsqrtf(v[idx] + BN_EPS);
        g_beta[layer * HH + idx] = (b[idx] - m[idx]) * alpha + be[idx];
    }
}

// ---------------- fp16 tensor-core GEMM: Y[N,128] = X[N,128] @ W[128,128] ---
// 128x128 tile / block, 8 warps, each warp m16 x n128, mma.m16n8k16 fp16.
// Smem rows padded to 136 halves (272 B) -> ldmatrix bank-conflict-free.
template <bool F32IN>
__global__ void __launch_bounds__(256) k_gemm_tc(const void* __restrict__ Xv,
                                                 const __half* __restrict__ W,
                                                 __half* __restrict__ Y) {
    extern __shared__ __half sh[];
    __half* As = sh;               // 128 x 136
    __half* Ws = sh + 128 * 136;   // 128 x 136 (row = k, cols = n)

    int tid = threadIdx.x;
    int row0 = blockIdx.x * 128;

    // load W tile (fp16, 128x128)
    const uint4* Wg = (const uint4*)W;
#pragma unroll
    for (int i = 0; i < 8; i++) {
        int idx = i * 256 + tid;          // uint4 = 8 halves; 2048 total
        int r = idx >> 4, c = (idx & 15) * 8;
        *(uint4*)&Ws[r * 136 + c] = Wg[idx];
    }
    // load A tile
    if (F32IN) {
        const float4* Xg = (const float4*)Xv;
#pragma unroll
        for (int i = 0; i < 16; i++) {
            int idx = i * 256 + tid;      // float4; 4096 total
            int r = idx >> 5, c = (idx & 31) * 4;
            float4 v = make_float4(0.f, 0.f, 0.f, 0.f);
            if (row0 + r < NN) v = Xg[(size_t)(row0 + r) * 32 + (idx & 31)];
            *(__half2*)&As[r * 136 + c]     = __floats2half2_rn(v.x, v.y);
            *(__half2*)&As[r * 136 + c + 2] = __floats2half2_rn(v.z, v.w);
        }
    } else {
        const uint4* Xg = (const uint4*)Xv;
#pragma unroll
        for (int i = 0; i < 8; i++) {
            int idx = i * 256 + tid;      // uint4 = 8 halves; 2048 total
            int r = idx >> 4, c = (idx & 15) * 8;
            uint4 v = make_uint4(0, 0, 0, 0);
            if (row0 + r < NN) v = Xg[(size_t)(row0 + r) * 16 + (idx & 15)];
            *(uint4*)&As[r * 136 + c] = v;
        }
    }
    __syncthreads();

    int wid = tid >> 5, lane = tid & 31;
    int m0 = wid * 16;

    float acc[16][4];
#pragma unroll
    for (int nt = 0; nt < 16; nt++)
#pragma unroll
        for (int c = 0; c < 4; c++) acc[nt][c] = 0.f;

#pragma unroll
    for (int ks = 0; ks < 8; ks++) {
        uint32_t a0, a1, a2, a3;
        uint32_t aaddr = s2u(&As[(m0 + (lane & 15)) * 136 + ks * 16 + (lane >> 4) * 8]);
        asm volatile("ldmatrix.sync.aligned.m8n8.x4.shared.b16 {%0,%1,%2,%3}, [%4];"
                     : "=r"(a0), "=r"(a1), "=r"(a2), "=r"(a3) : "r"(aaddr));
        // B fragments: one x4.trans per 16-column group (covers 2 n8 tiles)
#pragma unroll
        for (int ng = 0; ng < 8; ng++) {
            uint32_t b0, b1, b2, b3;
            uint32_t baddr = s2u(&Ws[(ks * 16 + (lane & 15)) * 136 +
                                     ng * 16 + (lane >> 4) * 8]);
            asm volatile("ldmatrix.sync.aligned.m8n8.x4.trans.shared.b16 {%0,%1,%2,%3}, [%4];"
                         : "=r"(b0), "=r"(b1), "=r"(b2), "=r"(b3) : "r"(baddr));
            int nt = ng * 2;
            asm volatile(
                "mma.sync.aligned.m16n8k16.row.col.f32.f16.f16.f32 "
                "{%0,%1,%2,%3}, {%4,%5,%6,%7}, {%8,%9}, {%0,%1,%2,%3};"
                : "+f"(acc[nt][0]), "+f"(acc[nt][1]), "+f"(acc[nt][2]), "+f"(acc[nt][3])
                : "r"(a0), "r"(a1), "r"(a2), "r"(a3), "r"(b0), "r"(b1));
            asm volatile(
                "mma.sync.aligned.m16n8k16.row.col.f32.f16.f16.f32 "
                "{%0,%1,%2,%3}, {%4,%5,%6,%7}, {%8,%9}, {%0,%1,%2,%3};"
                : "+f"(acc[nt + 1][0]), "+f"(acc[nt + 1][1]), "+f"(acc[nt + 1][2]), "+f"(acc[nt + 1][3])
                : "r"(a0), "r"(a1), "r"(a2), "r"(a3), "r"(b2), "r"(b3));
        }
    }

    int r0 = row0 + m0 + (lane >> 2);
    int cb = (lane & 3) * 2;
#pragma unroll
    for (int nt = 0; nt < 16; nt++) {
        if (r0 < NN)
            *(__half2*)&Y[(size_t)r0 * 128 + nt * 8 + cb] =
                __floats2half2_rn(acc[nt][0], acc[nt][1]);
        if (r0 + 8 < NN)
            *(__half2*)&Y[(size_t)(r0 + 8) * 128 + nt * 8 + cb] =
                __floats2half2_rn(acc[nt][2], acc[nt][3]);
    }
}

// ---------------- aggregation + folded-BN + ReLU (one warp per node) -------
// Edge metadata (col, dinv) fetched warp-wide (one lane per edge), then
// distributed via shfl -> row-gather loop has address-independent loads
// (unroll x4 => MLP~4) instead of a 2-deep L2 latency chain per edge.
template <bool FINAL>
__global__ void __launch_bounds__(256) k_agg16(const float* __restrict__ beta,
                                               const float* __restrict__ Wl,
                                               const int* __restrict__ batch) {
    int warp = (blockIdx.x * blockDim.x + threadIdx.x) >> 5;
    int lane = threadIdx.x & 31;
    if (warp >= NN) return;
    int i = warp;

    const uint2* T = (const uint2*)g_t;   // 32 x uint2 (4 halves) per row
    float di = g_dinv[i];

    uint2 u = T[(size_t)i * 32 + lane];
    float2 f0 = __half22float2(*(__half2*)&u.x);
    float2 f1 = __half22float2(*(__half2*)&u.y);
    float ws = di * di;
    float4 acc = make_float4(f0.x * ws, f0.y * ws, f1.x * ws, f1.y * ws);

    int e0 = g_rowptr[i];
    int cnt = g_rowptr[i + 1] - e0;

    for (int base = 0; base < cnt; base += 32) {
        int nb = min(32, cnt - base);
        int s_l = 0;
        float w_l = 0.f;
        if (lane < nb) {
            s_l = __ldg(&g_col[e0 + base + lane]);
            w_l = __ldg(&g_dinv[s_l]);
        }
        int j = 0;
        for (; j + 4 <= nb; j += 4) {
            int s0 = __shfl_sync(0xFFFFFFFFu, s_l, j);
            int s1 = __shfl_sync(0xFFFFFFFFu, s_l, j + 1);
            int s2 = __shfl_sync(0xFFFFFFFFu, s_l, j + 2);
            int s3 = __shfl_sync(0xFFFFFFFFu, s_l, j + 3);
            float w0 = __shfl_sync(0xFFFFFFFFu, w_l, j) * di;
            float w1 = __shfl_sync(0xFFFFFFFFu, w_l, j + 1) * di;
            float w2 = __shfl_sync(0xFFFFFFFFu, w_l, j + 2) * di;
            float w3 = __shfl_sync(0xFFFFFFFFu, w_l, j + 3) * di;
            uint2 v0 = T[(size_t)s0 * 32 + lane];
            uint2 v1 = T[(size_t)s1 * 32 + lane];
            uint2 v2 = T[(size_t)s2 * 32 + lane];
            uint2 v3 = T[(size_t)s3 * 32 + lane];
            float2 a, b;
            a = __half22float2(*(__half2*)&v0.x); b = __half22float2(*(__half2*)&v0.y);
            acc.x = fmaf(w0, a.x, acc.x); acc.y = fmaf(w0, a.y, acc.y);
            acc.z = fmaf(w0, b.x, acc.z); acc.w = fmaf(w0, b.y, acc.w);
            a = __half22float2(*(__half2*)&v1.x); b = __half22float2(*(__half2*)&v1.y);
            acc.x = fmaf(w1, a.x, acc.x); acc.y = fmaf(w1, a.y, acc.y);
            acc.z = fmaf(w1, b.x, acc.z); acc.w = fmaf(w1, b.y, acc.w);
            a = __half22float2(*(__half2*)&v2.x); b = __half22float2(*(__half2*)&v2.y);
            acc.x = fmaf(w2, a.x, acc.x); acc.y = fmaf(w2, a.y, acc.y);
            acc.z = fmaf(w2, b.x, acc.z); acc.w = fmaf(w2, b.y, acc.w);
            a = __half22float2(*(__half2*)&v3.x); b = __half22float2(*(__half2*)&v3.y);
            acc.x = fmaf(w3, a.x, acc.x); acc.y = fmaf(w3, a.y, acc.y);
            acc.z = fmaf(w3, b.x, acc.z); acc.w = fmaf(w3, b.y, acc.w);
        }
        for (; j < nb; j++) {
            int s = __shfl_sync(0xFFFFFFFFu, s_l, j);
            float w = __shfl_sync(0xFFFFFFFFu, w_l, j) * di;
            uint2 v = T[(size_t)s * 32 + lane];
            float2 a = __half22float2(*(__half2*)&v.x);
            float2 b = __half22float2(*(__half2*)&v.y);
            acc.x = fmaf(w, a.x, acc.x); acc.y = fmaf(w, a.y, acc.y);
            acc.z = fmaf(w, b.x, acc.z); acc.w = fmaf(w, b.y, acc.w);
        }
    }

    float4 be = ((const float4*)beta)[lane];
    float4 y;
    y.x = fmaxf(0.f, acc.x + be.x);
    y.y = fmaxf(0.f, acc.y + be.y);
    y.z = fmaxf(0.f, acc.z + be.z);
    y.w = fmaxf(0.f, acc.w + be.w);

    if (!FINAL) {
        uint2 o;
        *(__half2*)&o.x = __floats2half2_rn(y.x, y.y);
        *(__half2*)&o.y = __floats2half2_rn(y.z, y.w);
        ((uint2*)g_h)[(size_t)i * 32 + lane] = o;
    } else {
        float4 wl = ((const float4*)Wl)[lane];
        float s = y.x * wl.x + y.y * wl.y + y.z * wl.z + y.w * wl.w;
#pragma unroll
        for (int off = 16; off > 0; off >>= 1)
            s += __shfl_xor_sync(0xFFFFFFFFu, s, off);
        if (lane == 0) atomicAdd(&g_gsum[batch[i]], s);
    }
}

__global__ void k_final(float* __restrict__ out, const float* __restrict__ bl) {
    int g = blockIdx.x * blockDim.x + threadIdx.x;
    if (g < GG) out[g] = g_gsum[g] / fmaxf((float)g_gcnt[g], 1.0f) + bl[0];
}

// ---------------- host launcher --------------------------------------------
extern "C" void kernel_launch(void* const* d_in, const int* in_sizes, int n_in,
                              void* d_out, int out_size) {
    const float* x     = (const float*)d_in[0];
    const int*   ei    = (const int*)d_in[1];
    const int*   batch = (const int*)d_in[2];
    const float* W1 = (const float*)d_in[3];
    const float* b1 = (const float*)d_in[4];
    const float* g1 = (const float*)d_in[5];
    const float* be1 = (const float*)d_in[6];
    const float* m1 = (const float*)d_in[7];
    const float* v1 = (const float*)d_in[8];
    const float* W2 = (const float*)d_in[9];
    const float* b2 = (const float*)d_in[10];
    const float* g2 = (const float*)d_in[11];
    const float* be2 = (const float*)d_in[12];
    const float* m2 = (const float*)d_in[13];
    const float* v2 = (const float*)d_in[14];
    const float* W3 = (const float*)d_in[15];
    const float* b3 = (const float*)d_in[16];
    const float* g3 = (const float*)d_in[17];
    const float* be3 = (const float*)d_in[18];
    const float* m3 = (const float*)d_in[19];
    const float* v3 = (const float*)d_in[20];
    const float* Wl = (const float*)d_in[21];
    const float* bl = (const float*)d_in[22];

    __half *t, *h, *Wh;
    float *beta;
    cudaGetSymbolAddress((void**)&t, g_t);
    cudaGetSymbolAddress((void**)&h, g_h);
    cudaGetSymbolAddress((void**)&Wh, g_Wh);
    cudaGetSymbolAddress((void**)&beta, g_beta);

    const int GEMM_SMEM = 2 * 128 * 136 * (int)sizeof(__half);   // 69632
    cudaFuncSetAttribute(k_gemm_tc<true>,  cudaFuncAttributeMaxDynamicSharedMemorySize, GEMM_SMEM);
    cudaFuncSetAttribute(k_gemm_tc<false>, cudaFuncAttributeMaxDynamicSharedMemorySize, GEMM_SMEM);

    const int TPB = 256;
    // ---- graph preprocessing (CSR by dst, dinv, per-graph counts)
    k_zero<<<(NN + TPB - 1) / TPB, TPB>>>();
    k_hist<<<(EE + TPB - 1) / TPB, TPB>>>(ei, batch);
    k_scan_local<<<NB, SCAN_B>>>();
    k_scan_part<<<1, 128>>>();
    k_scan_add<<<(NN + TPB) / TPB, TPB>>>();
    k_fill<<<(EE + TPB - 1) / TPB, TPB>>>(ei);

    // ---- weight prep: fold BN scale into W, convert to fp16 (all 3 layers)
    {
        dim3 grid(64, 3);
        k_prep_w<<<grid, 256>>>(W1, W2, W3, b1, b2, b3, g1, g2, g3,
                                be1, be2, be3, m1, m2, m3, v1, v2, v3);
    }

    const int GEMM_BLOCKS = (NN + 127) / 128;           // 782
    const int AGG_BLOCKS = (NN * 32 + TPB - 1) / TPB;   // 12500

    // ---- layer 1
    k_gemm_tc<true><<<GEMM_BLOCKS, 256, GEMM_SMEM>>>(x, Wh, t);
    k_agg16<false><<<AGG_BLOCKS, TPB>>>(beta, nullptr, nullptr);
    // ---- layer 2
    k_gemm_tc<false><<<GEMM_BLOCKS, 256, GEMM_SMEM>>>(h, Wh + HH * HH, t);
    k_agg16<false><<<AGG_BLOCKS, TPB>>>(beta + HH, nullptr, nullptr);
    // ---- layer 3 (fused mean-pool + linear head via per-node dot)
    k_gemm_tc<false><<<GEMM_BLOCKS, 256, GEMM_SMEM>>>(h, Wh + 2 * HH * HH, t);
    k_agg16<true><<<AGG_BLOCKS, TPB>>>(beta + 2 * HH, Wl, batch);

    k_final<<<(GG + TPB - 1) / TPB, TPB>>>((float*)d_out, bl);
}

// round 5
// speedup vs baseline: 1.1064x; 1.1064x over previous
#include <cuda_runtime.h>
#include <cuda_fp16.h>
#include <cstdint>

#define NN 100000
#define EE 1600000
#define HH 128
#define GG 512
#define BN_EPS 1e-5f
#define SCAN_B 1024
#define NB ((NN + SCAN_B - 1) / SCAN_B)   // 98 scan blocks

// ---------------- scratch (device globals: no allocation allowed) -----------
__device__ __half g_t[(size_t)NN * HH];   // GEMM output t = h @ W' (fp16)
__device__ __half g_h[(size_t)NN * HH];   // activated hidden (fp16)
__device__ __half g_Wh[3 * HH * HH];      // BN-folded fp16 weights
__device__ float  g_beta[3 * HH];         // BN-folded shifts
__device__ float  g_dinv[NN];
__device__ int    g_deg[NN];
__device__ int    g_rowptr[NN + 1];
__device__ int    g_cursor[NN];
__device__ int    g_col[EE];
__device__ float  g_gsum[GG];
__device__ int    g_gcnt[GG];
__device__ int    g_part[NB];

__device__ __forceinline__ uint32_t s2u(const void* p) {
    return (uint32_t)__cvta_generic_to_shared(p);
}

// ---------------- preprocessing kernels ------------------------------------
__global__ void k_zero() {
    int i = blockIdx.x * blockDim.x + threadIdx.x;
    if (i < NN) g_deg[i] = 0;
    if (i < GG) { g_gsum[i] = 0.0f; g_gcnt[i] = 0; }
}

// degree histogram over dst + per-graph node counts (fused)
__global__ void k_hist(const int* __restrict__ ei, const int* __restrict__ batch) {
    int e = blockIdx.x * blockDim.x + threadIdx.x;
    if (e < EE) atomicAdd(&g_deg[ei[EE + e]], 1);
    if (e < NN) atomicAdd(&g_gcnt[batch[e]], 1);
}

__global__ void k_scan_local() {
    __shared__ int sh[SCAN_B];
    int tx = threadIdx.x;
    int i = blockIdx.x * SCAN_B + tx;
    int v = (i < NN) ? g_deg[i] : 0;
    if (i < NN) g_dinv[i] = rsqrtf((float)(v + 1));   // fused dinv (+1 self-loop)
    sh[tx] = v;
    __syncthreads();
    for (int off = 1; off < SCAN_B; off <<= 1) {
        int t = (tx >= off) ? sh[tx - off] : 0;
        __syncthreads();
        sh[tx] += t;
        __syncthreads();
    }
    if (i < NN) g_rowptr[i] = sh[tx] - v;        // exclusive
    if (tx == SCAN_B - 1) g_part[blockIdx.x] = sh[tx];
}

__global__ void k_scan_part() {
    __shared__ int sh[128];
    int tx = threadIdx.x;
    int v = (tx < NB) ? g_part[tx] : 0;
    sh[tx] = v;
    __syncthreads();
    for (int off = 1; off < 128; off <<= 1) {
        int t = (tx >= off) ? sh[tx - off] : 0;
        __syncthreads();
        sh[tx] += t;
        __syncthreads();
    }
    if (tx < NB) g_part[tx] = sh[tx] - v;        // exclusive block offsets
}

__global__ void k_scan_add() {
    int i = blockIdx.x * blockDim.x + threadIdx.x;
    if (i < NN) {
        int v = g_rowptr[i] + g_part[i >> 10];
        g_rowptr[i] = v;
        g_cursor[i] = v;
    }
    if (i == 0) g_rowptr[NN] = EE;
}

__global__ void k_fill(const int* __restrict__ ei) {
    int e = blockIdx.x * blockDim.x + threadIdx.x;
    if (e < EE) {
        int src = ei[e];
        int dst = ei[EE + e];
        int p = atomicAdd(&g_cursor[dst], 1);
        g_col[p] = src;
    }
}

// Fold BN scale into W columns (fp16) for all 3 layers, compute folded shifts.
__global__ void k_prep_w(const float* __restrict__ W1v, const float* __restrict__ W2v,
                         const float* __restrict__ W3v,
                         const float* __restrict__ b1v, const float* __restrict__ b2v,
                         const float* __restrict__ b3v,
                         const float* __restrict__ ga1, const float* __restrict__ ga2,
                         const float* __restrict__ ga3,
                         const float* __restrict__ be1, const float* __restrict__ be2,
                         const float* __restrict__ be3,
                         const float* __restrict__ m1v, const float* __restrict__ m2v,
                         const float* __restrict__ m3v,
                         const float* __restrict__ v1v, const float* __restrict__ v2v,
                         const float* __restrict__ v3v) {
    int layer = blockIdx.y;
    const float* W  = layer == 0 ? W1v : layer == 1 ? W2v : W3v;
    const float* b  = layer == 0 ? b1v : layer == 1 ? b2v : b3v;
    const float* ga = layer == 0 ? ga1 : layer == 1 ? ga2 : ga3;
    const float* be = layer == 0 ? be1 : layer == 1 ? be2 : be3;
    const float* m  = layer == 0 ? m1v : layer == 1 ? m2v : m3v;
    const float* v  = layer == 0 ? v1v : layer == 1 ? v2v : v3v;
    int idx = blockIdx.x * blockDim.x + threadIdx.x;
    if (idx < HH * HH) {
        int n = idx & (HH - 1);
        float alpha = ga[n] * rsqrtf(v[n] + BN_EPS);
        g_Wh[layer * HH * HH + idx] = __float2half(W[idx] * alpha);
    }
    if (idx < HH) {
        float alpha = ga[idx] * rsqrtf(v[idx] + BN_EPS);
        g_beta[layer * HH + idx] = (b[idx] - m[idx]) * alpha + be[idx];
    }
}

// ---------------- fp16 tensor-core GEMM: Y[N,128] = X[N,128] @ W[128,128] ---
// 128x128 tile / block, 8 warps, each warp m16 x n128, mma.m16n8k16 fp16.
// Smem rows padded to 136 halves (272 B) -> ldmatrix bank-conflict-free.
template <bool F32IN>
__global__ void __launch_bounds__(256) k_gemm_tc(const void* __restrict__ Xv,
                                                 const __half* __restrict__ W,
                                                 __half* __restrict__ Y) {
    extern __shared__ __half sh[];
    __half* As = sh;               // 128 x 136
    __half* Ws = sh + 128 * 136;   // 128 x 136 (row = k, cols = n)

    int tid = threadIdx.x;
    int row0 = blockIdx.x * 128;

    // load W tile (fp16, 128x128)
    const uint4* Wg = (const uint4*)W;
#pragma unroll
    for (int i = 0; i < 8; i++) {
        int idx = i * 256 + tid;          // uint4 = 8 halves; 2048 total
        int r = idx >> 4, c = (idx & 15) * 8;
        *(uint4*)&Ws[r * 136 + c] = Wg[idx];
    }
    // load A tile
    if (F32IN) {
        const float4* Xg = (const float4*)Xv;
#pragma unroll
        for (int i = 0; i < 16; i++) {
            int idx = i * 256 + tid;      // float4; 4096 total
            int r = idx >> 5, c = (idx & 31) * 4;
            float4 v = make_float4(0.f, 0.f, 0.f, 0.f);
            if (row0 + r < NN) v = Xg[(size_t)(row0 + r) * 32 + (idx & 31)];
            *(__half2*)&As[r * 136 + c]     = __floats2half2_rn(v.x, v.y);
            *(__half2*)&As[r * 136 + c + 2] = __floats2half2_rn(v.z, v.w);
        }
    } else {
        const uint4* Xg = (const uint4*)Xv;
#pragma unroll
        for (int i = 0; i < 8; i++) {
            int idx = i * 256 + tid;      // uint4 = 8 halves; 2048 total
            int r = idx >> 4, c = (idx & 15) * 8;
            uint4 v = make_uint4(0, 0, 0, 0);
            if (row0 + r < NN) v = Xg[(size_t)(row0 + r) * 16 + (idx & 15)];
            *(uint4*)&As[r * 136 + c] = v;
        }
    }
    __syncthreads();

    int wid = tid >> 5, lane = tid & 31;
    int m0 = wid * 16;

    float acc[16][4];
#pragma unroll
    for (int nt = 0; nt < 16; nt++)
#pragma unroll
        for (int c = 0; c < 4; c++) acc[nt][c] = 0.f;

#pragma unroll
    for (int ks = 0; ks < 8; ks++) {
        uint32_t a0, a1, a2, a3;
        uint32_t aaddr = s2u(&As[(m0 + (lane & 15)) * 136 + ks * 16 + (lane >> 4) * 8]);
        asm volatile("ldmatrix.sync.aligned.m8n8.x4.shared.b16 {%0,%1,%2,%3}, [%4];"
                     : "=r"(a0), "=r"(a1), "=r"(a2), "=r"(a3) : "r"(aaddr));
        // B fragments: one x4.trans per 16-column group (covers 2 n8 tiles)
#pragma unroll
        for (int ng = 0; ng < 8; ng++) {
            uint32_t b0, b1, b2, b3;
            uint32_t baddr = s2u(&Ws[(ks * 16 + (lane & 15)) * 136 +
                                     ng * 16 + (lane >> 4) * 8]);
            asm volatile("ldmatrix.sync.aligned.m8n8.x4.trans.shared.b16 {%0,%1,%2,%3}, [%4];"
                         : "=r"(b0), "=r"(b1), "=r"(b2), "=r"(b3) : "r"(baddr));
            int nt = ng * 2;
            asm volatile(
                "mma.sync.aligned.m16n8k16.row.col.f32.f16.f16.f32 "
                "{%0,%1,%2,%3}, {%4,%5,%6,%7}, {%8,%9}, {%0,%1,%2,%3};"
                : "+f"(acc[nt][0]), "+f"(acc[nt][1]), "+f"(acc[nt][2]), "+f"(acc[nt][3])
                : "r"(a0), "r"(a1), "r"(a2), "r"(a3), "r"(b0), "r"(b1));
            asm volatile(
                "mma.sync.aligned.m16n8k16.row.col.f32.f16.f16.f32 "
                "{%0,%1,%2,%3}, {%4,%5,%6,%7}, {%8,%9}, {%0,%1,%2,%3};"
                : "+f"(acc[nt + 1][0]), "+f"(acc[nt + 1][1]), "+f"(acc[nt + 1][2]), "+f"(acc[nt + 1][3])
                : "r"(a0), "r"(a1), "r"(a2), "r"(a3), "r"(b2), "r"(b3));
        }
    }

    int r0 = row0 + m0 + (lane >> 2);
    int cb = (lane & 3) * 2;
#pragma unroll
    for (int nt = 0; nt < 16; nt++) {
        if (r0 < NN)
            *(__half2*)&Y[(size_t)r0 * 128 + nt * 8 + cb] =
                __floats2half2_rn(acc[nt][0], acc[nt][1]);
        if (r0 + 8 < NN)
            *(__half2*)&Y[(size_t)(r0 + 8) * 128 + nt * 8 + cb] =
                __floats2half2_rn(acc[nt][2], acc[nt][3]);
    }
}

// ---------------- aggregation + folded-BN + ReLU (one warp per node) -------
// Simple per-edge loop, manually unrolled x4: independent scalar loads give
// MLP~4 at each level of the col->dinv->row chain without shfl overhead.
template <bool FINAL>
__global__ void __launch_bounds__(256) k_agg16(const float* __restrict__ beta,
                                               const float* __restrict__ Wl,
                                               const int* __restrict__ batch) {
    int warp = (blockIdx.x * blockDim.x + threadIdx.x) >> 5;
    int lane = threadIdx.x & 31;
    if (warp >= NN) return;
    int i = warp;

    const uint2* T = (const uint2*)g_t;   // 32 x uint2 (4 halves) per row
    float di = g_dinv[i];

    uint2 u = T[(size_t)i * 32 + lane];
    float2 f0 = __half22float2(*(__half2*)&u.x);
    float2 f1 = __half22float2(*(__half2*)&u.y);
    float ws = di * di;
    float4 acc = make_float4(f0.x * ws, f0.y * ws, f1.x * ws, f1.y * ws);

    int e = g_rowptr[i];
    int e1 = g_rowptr[i + 1];

    for (; e + 4 <= e1; e += 4) {
        int s0 = __ldg(&g_col[e]);
        int s1 = __ldg(&g_col[e + 1]);
        int s2 = __ldg(&g_col[e + 2]);
        int s3 = __ldg(&g_col[e + 3]);
        float w0 = di * __ldg(&g_dinv[s0]);
        float w1 = di * __ldg(&g_dinv[s1]);
        float w2 = di * __ldg(&g_dinv[s2]);
        float w3 = di * __ldg(&g_dinv[s3]);
        uint2 v0 = T[(size_t)s0 * 32 + lane];
        uint2 v1 = T[(size_t)s1 * 32 + lane];
        uint2 v2 = T[(size_t)s2 * 32 + lane];
        uint2 v3 = T[(size_t)s3 * 32 + lane];
        float2 a, b;
        a = __half22float2(*(__half2*)&v0.x); b = __half22float2(*(__half2*)&v0.y);
        acc.x = fmaf(w0, a.x, acc.x); acc.y = fmaf(w0, a.y, acc.y);
        acc.z = fmaf(w0, b.x, acc.z); acc.w = fmaf(w0, b.y, acc.w);
        a = __half22float2(*(__half2*)&v1.x); b = __half22float2(*(__half2*)&v1.y);
        acc.x = fmaf(w1, a.x, acc.x); acc.y = fmaf(w1, a.y, acc.y);
        acc.z = fmaf(w1, b.x, acc.z); acc.w = fmaf(w1, b.y, acc.w);
        a = __half22float2(*(__half2*)&v2.x); b = __half22float2(*(__half2*)&v2.y);
        acc.x = fmaf(w2, a.x, acc.x); acc.y = fmaf(w2, a.y, acc.y);
        acc.z = fmaf(w2, b.x, acc.z); acc.w = fmaf(w2, b.y, acc.w);
        a = __half22float2(*(__half2*)&v3.x); b = __half22float2(*(__half2*)&v3.y);
        acc.x = fmaf(w3, a.x, acc.x); acc.y = fmaf(w3, a.y, acc.y);
        acc.z = fmaf(w3, b.x, acc.z); acc.w = fmaf(w3, b.y, acc.w);
    }
    for (; e < e1; ++e) {
        int s = __ldg(&g_col[e]);
        float w = di * __ldg(&g_dinv[s]);
        uint2 v = T[(size_t)s * 32 + lane];
        float2 a = __half22float2(*(__half2*)&v.x);
        float2 b = __half22float2(*(__half2*)&v.y);
        acc.x = fmaf(w, a.x, acc.x); acc.y = fmaf(w, a.y, acc.y);
        acc.z = fmaf(w, b.x, acc.z); acc.w = fmaf(w, b.y, acc.w);
    }

    float4 be = ((const float4*)beta)[lane];
    float4 y;
    y.x = fmaxf(0.f, acc.x + be.x);
    y.y = fmaxf(0.f, acc.y + be.y);
    y.z = fmaxf(0.f, acc.z + be.z);
    y.w = fmaxf(0.f, acc.w + be.w);

    if (!FINAL) {
        uint2 o;
        *(__half2*)&o.x = __floats2half2_rn(y.x, y.y);
        *(__half2*)&o.y = __floats2half2_rn(y.z, y.w);
        ((uint2*)g_h)[(size_t)i * 32 + lane] = o;
    } else {
        float4 wl = ((const float4*)Wl)[lane];
        float s = y.x * wl.x + y.y * wl.y + y.z * wl.z + y.w * wl.w;
#pragma unroll
        for (int off = 16; off > 0; off >>= 1)
            s += __shfl_xor_sync(0xFFFFFFFFu, s, off);
        if (lane == 0) atomicAdd(&g_gsum[batch[i]], s);
    }
}

__global__ void k_final(float* __restrict__ out, const float* __restrict__ bl) {
    int g = blockIdx.x * blockDim.x + threadIdx.x;
    if (g < GG) out[g] = g_gsum[g] / fmaxf((float)g_gcnt[g], 1.0f) + bl[0];
}

// ---------------- host launcher --------------------------------------------
extern "C" void kernel_launch(void* const* d_in, const int* in_sizes, int n_in,
                              void* d_out, int out_size) {
    const float* x     = (const float*)d_in[0];
    const int*   ei    = (const int*)d_in[1];
    const int*   batch = (const int*)d_in[2];
    const float* W1 = (const float*)d_in[3];
    const float* b1 = (const float*)d_in[4];
    const float* g1 = (const float*)d_in[5];
    const float* be1 = (const float*)d_in[6];
    const float* m1 = (const float*)d_in[7];
    const float* v1 = (const float*)d_in[8];
    const float* W2 = (const float*)d_in[9];
    const float* b2 = (const float*)d_in[10];
    const float* g2 = (const float*)d_in[11];
    const float* be2 = (const float*)d_in[12];
    const float* m2 = (const float*)d_in[13];
    const float* v2 = (const float*)d_in[14];
    const float* W3 = (const float*)d_in[15];
    const float* b3 = (const float*)d_in[16];
    const float* g3 = (const float*)d_in[17];
    const float* be3 = (const float*)d_in[18];
    const float* m3 = (const float*)d_in[19];
    const float* v3 = (const float*)d_in[20];
    const float* Wl = (const float*)d_in[21];
    const float* bl = (const float*)d_in[22];

    __half *t, *h, *Wh;
    float *beta;
    cudaGetSymbolAddress((void**)&t, g_t);
    cudaGetSymbolAddress((void**)&h, g_h);
    cudaGetSymbolAddress((void**)&Wh, g_Wh);
    cudaGetSymbolAddress((void**)&beta, g_beta);

    const int GEMM_SMEM = 2 * 128 * 136 * (int)sizeof(__half);   // 69632
    cudaFuncSetAttribute(k_gemm_tc<true>,  cudaFuncAttributeMaxDynamicSharedMemorySize, GEMM_SMEM);
    cudaFuncSetAttribute(k_gemm_tc<false>, cudaFuncAttributeMaxDynamicSharedMemorySize, GEMM_SMEM);

    const int TPB = 256;
    // ---- graph preprocessing (CSR by dst, dinv, per-graph counts)
    k_zero<<<(NN + TPB - 1) / TPB, TPB>>>();
    k_hist<<<(EE + TPB - 1) / TPB, TPB>>>(ei, batch);
    k_scan_local<<<NB, SCAN_B>>>();
    k_scan_part<<<1, 128>>>();
    k_scan_add<<<(NN + TPB) / TPB, TPB>>>();
    k_fill<<<(EE + TPB - 1) / TPB, TPB>>>(ei);

    // ---- weight prep: fold BN scale into W, convert to fp16 (all 3 layers)
    {
        dim3 grid(64, 3);
        k_prep_w<<<grid, 256>>>(W1, W2, W3, b1, b2, b3, g1, g2, g3,
                                be1, be2, be3, m1, m2, m3, v1, v2, v3);
    }

    const int GEMM_BLOCKS = (NN + 127) / 128;           // 782
    const int AGG_BLOCKS = (NN * 32 + TPB - 1) / TPB;   // 12500

    // ---- layer 1
    k_gemm_tc<true><<<GEMM_BLOCKS, 256, GEMM_SMEM>>>(x, Wh, t);
    k_agg16<false><<<AGG_BLOCKS, TPB>>>(beta, nullptr, nullptr);
    // ---- layer 2
    k_gemm_tc<false><<<GEMM_BLOCKS, 256, GEMM_SMEM>>>(h, Wh + HH * HH, t);
    k_agg16<false><<<AGG_BLOCKS, TPB>>>(beta + HH, nullptr, nullptr);
    // ---- layer 3 (fused mean-pool + linear head via per-node dot)
    k_gemm_tc<false><<<GEMM_BLOCKS, 256, GEMM_SMEM>>>(h, Wh + 2 * HH * HH, t);
    k_agg16<true><<<AGG_BLOCKS, TPB>>>(beta + 2 * HH, Wl, batch);

    k_final<<<(GG + TPB - 1) / TPB, TPB>>>((float*)d_out, bl);
}

// round 6
// speedup vs baseline: 1.2036x; 1.0878x over previous
#include <cuda_runtime.h>
#include <cuda_fp16.h>
#include <cstdint>

#define NN 100000
#define EE 1600000
#define HH 128
#define GG 512
#define BN_EPS 1e-5f
#define SCAN_B 1024
#define NB ((NN + SCAN_B - 1) / SCAN_B)   // 98 scan blocks

// ---------------- scratch (device globals: no allocation allowed) -----------
__device__ __half g_t[(size_t)NN * HH];   // GEMM output t' = dinv .* (h @ W') (fp16)
__device__ __half g_h[(size_t)NN * HH];   // activated hidden (fp16)
__device__ __half g_Wh[3 * HH * HH];      // BN-folded fp16 weights
__device__ float  g_beta[3 * HH];         // BN-folded shifts
__device__ float  g_dinv[NN];
__device__ int    g_deg[NN];
__device__ int    g_rowptr[NN + 1];
__device__ int    g_cursor[NN];
__device__ int    g_col[EE];
__device__ float  g_gsum[GG];
__device__ int    g_gcnt[GG];
__device__ int    g_part[NB];

__device__ __forceinline__ uint32_t s2u(const void* p) {
    return (uint32_t)__cvta_generic_to_shared(p);
}

// ---------------- preprocessing kernels ------------------------------------
__global__ void k_zero() {
    int i = blockIdx.x * blockDim.x + threadIdx.x;
    if (i < NN) g_deg[i] = 0;
    if (i < GG) { g_gsum[i] = 0.0f; g_gcnt[i] = 0; }
}

// degree histogram over dst + per-graph node counts (fused)
__global__ void k_hist(const int* __restrict__ ei, const int* __restrict__ batch) {
    int e = blockIdx.x * blockDim.x + threadIdx.x;
    if (e < EE) atomicAdd(&g_deg[ei[EE + e]], 1);
    if (e < NN) atomicAdd(&g_gcnt[batch[e]], 1);
}

__global__ void k_scan_local() {
    __shared__ int sh[SCAN_B];
    int tx = threadIdx.x;
    int i = blockIdx.x * SCAN_B + tx;
    int v = (i < NN) ? g_deg[i] : 0;
    if (i < NN) g_dinv[i] = rsqrtf((float)(v + 1));   // fused dinv (+1 self-loop)
    sh[tx] = v;
    __syncthreads();
    for (int off = 1; off < SCAN_B; off <<= 1) {
        int t = (tx >= off) ? sh[tx - off] : 0;
        __syncthreads();
        sh[tx] += t;
        __syncthreads();
    }
    if (i < NN) g_rowptr[i] = sh[tx] - v;        // exclusive
    if (tx == SCAN_B - 1) g_part[blockIdx.x] = sh[tx];
}

__global__ void k_scan_part() {
    __shared__ int sh[128];
    int tx = threadIdx.x;
    int v = (tx < NB) ? g_part[tx] : 0;
    sh[tx] = v;
    __syncthreads();
    for (int off = 1; off < 128; off <<= 1) {
        int t = (tx >= off) ? sh[tx - off] : 0;
        __syncthreads();
        sh[tx] += t;
        __syncthreads();
    }
    if (tx < NB) g_part[tx] = sh[tx] - v;        // exclusive block offsets
}

__global__ void k_scan_add() {
    int i = blockIdx.x * blockDim.x + threadIdx.x;
    if (i < NN) {
        int v = g_rowptr[i] + g_part[i >> 10];
        g_rowptr[i] = v;
        g_cursor[i] = v;
    }
    if (i == 0) g_rowptr[NN] = EE;
}

__global__ void k_fill(const int* __restrict__ ei) {
    int e = blockIdx.x * blockDim.x + threadIdx.x;
    if (e < EE) {
        int src = ei[e];
        int dst = ei[EE + e];
        int p = atomicAdd(&g_cursor[dst], 1);
        g_col[p] = src;
    }
}

// Fold BN scale into W columns (fp16) for all 3 layers, compute folded shifts.
__global__ void k_prep_w(const float* __restrict__ W1v, const float* __restrict__ W2v,
                         const float* __restrict__ W3v,
                         const float* __restrict__ b1v, const float* __restrict__ b2v,
                         const float* __restrict__ b3v,
                         const float* __restrict__ ga1, const float* __restrict__ ga2,
                         const float* __restrict__ ga3,
                         const float* __restrict__ be1, const float* __restrict__ be2,
                         const float* __restrict__ be3,
                         const float* __restrict__ m1v, const float* __restrict__ m2v,
                         const float* __restrict__ m3v,
                         const float* __restrict__ v1v, const float* __restrict__ v2v,
                         const float* __restrict__ v3v) {
    int layer = blockIdx.y;
    const float* W  = layer == 0 ? W1v : layer == 1 ? W2v : W3v;
    const float* b  = layer == 0 ? b1v : layer == 1 ? b2v : b3v;
    const float* ga = layer == 0 ? ga1 : layer == 1 ? ga2 : ga3;
    const float* be = layer == 0 ? be1 : layer == 1 ? be2 : be3;
    const float* m  = layer == 0 ? m1v : layer == 1 ? m2v : m3v;
    const float* v  = layer == 0 ? v1v : layer == 1 ? v2v : v3v;
    int idx = blockIdx.x * blockDim.x + threadIdx.x;
    if (idx < HH * HH) {
        int n = idx & (HH - 1);
        float alpha = ga[n] * rsqrtf(v[n] + BN_EPS);
        g_Wh[layer * HH * HH + idx] = __float2half(W[idx] * alpha);
    }
    if (idx < HH) {
        float alpha = ga[idx] * rsqrtf(v[idx] + BN_EPS);
        g_beta[layer * HH + idx] = (b[idx] - m[idx]) * alpha + be[idx];
    }
}

// ---------------- fp16 tensor-core GEMM + dinv prescale epilogue -----------
// Y[i,:] = dinv[i] * (X[i,:] @ W)   -> agg inner loop needs NO per-edge dinv.
template <bool F32IN>
__global__ void __launch_bounds__(256) k_gemm_tc(const void* __restrict__ Xv,
                                                 const __half* __restrict__ W,
                                                 __half* __restrict__ Y) {
    extern __shared__ __half sh[];
    __half* As = sh;               // 128 x 136
    __half* Ws = sh + 128 * 136;   // 128 x 136 (row = k, cols = n)

    int tid = threadIdx.x;
    int row0 = blockIdx.x * 128;

    // load W tile (fp16, 128x128)
    const uint4* Wg = (const uint4*)W;
#pragma unroll
    for (int i = 0; i < 8; i++) {
        int idx = i * 256 + tid;          // uint4 = 8 halves; 2048 total
        int r = idx >> 4, c = (idx & 15) * 8;
        *(uint4*)&Ws[r * 136 + c] = Wg[idx];
    }
    // load A tile
    if (F32IN) {
        const float4* Xg = (const float4*)Xv;
#pragma unroll
        for (int i = 0; i < 16; i++) {
            int idx = i * 256 + tid;      // float4; 4096 total
            int r = idx >> 5, c = (idx & 31) * 4;
            float4 v = make_float4(0.f, 0.f, 0.f, 0.f);
            if (row0 + r < NN) v = Xg[(size_t)(row0 + r) * 32 + (idx & 31)];
            *(__half2*)&As[r * 136 + c]     = __floats2half2_rn(v.x, v.y);
            *(__half2*)&As[r * 136 + c + 2] = __floats2half2_rn(v.z, v.w);
        }
    } else {
        const uint4* Xg = (const uint4*)Xv;
#pragma unroll
        for (int i = 0; i < 8; i++) {
            int idx = i * 256 + tid;      // uint4 = 8 halves; 2048 total
            int r = idx >> 4, c = (idx & 15) * 8;
            uint4 v = make_uint4(0, 0, 0, 0);
            if (row0 + r < NN) v = Xg[(size_t)(row0 + r) * 16 + (idx & 15)];
            *(uint4*)&As[r * 136 + c] = v;
        }
    }
    __syncthreads();

    int wid = tid >> 5, lane = tid & 31;
    int m0 = wid * 16;

    float acc[16][4];
#pragma unroll
    for (int nt = 0; nt < 16; nt++)
#pragma unroll
        for (int c = 0; c < 4; c++) acc[nt][c] = 0.f;

#pragma unroll
    for (int ks = 0; ks < 8; ks++) {
        uint32_t a0, a1, a2, a3;
        uint32_t aaddr = s2u(&As[(m0 + (lane & 15)) * 136 + ks * 16 + (lane >> 4) * 8]);
        asm volatile("ldmatrix.sync.aligned.m8n8.x4.shared.b16 {%0,%1,%2,%3}, [%4];"
                     : "=r"(a0), "=r"(a1), "=r"(a2), "=r"(a3) : "r"(aaddr));
        // B fragments: one x4.trans per 16-column group (covers 2 n8 tiles)
#pragma unroll
        for (int ng = 0; ng < 8; ng++) {
            uint32_t b0, b1, b2, b3;
            uint32_t baddr = s2u(&Ws[(ks * 16 + (lane & 15)) * 136 +
                                     ng * 16 + (lane >> 4) * 8]);
            asm volatile("ldmatrix.sync.aligned.m8n8.x4.trans.shared.b16 {%0,%1,%2,%3}, [%4];"
                         : "=r"(b0), "=r"(b1), "=r"(b2), "=r"(b3) : "r"(baddr));
            int nt = ng * 2;
            asm volatile(
                "mma.sync.aligned.m16n8k16.row.col.f32.f16.f16.f32 "
                "{%0,%1,%2,%3}, {%4,%5,%6,%7}, {%8,%9}, {%0,%1,%2,%3};"
                : "+f"(acc[nt][0]), "+f"(acc[nt][1]), "+f"(acc[nt][2]), "+f"(acc[nt][3])
                : "r"(a0), "r"(a1), "r"(a2), "r"(a3), "r"(b0), "r"(b1));
            asm volatile(
                "mma.sync.aligned.m16n8k16.row.col.f32.f16.f16.f32 "
                "{%0,%1,%2,%3}, {%4,%5,%6,%7}, {%8,%9}, {%0,%1,%2,%3};"
                : "+f"(acc[nt + 1][0]), "+f"(acc[nt + 1][1]), "+f"(acc[nt + 1][2]), "+f"(acc[nt + 1][3])
                : "r"(a0), "r"(a1), "r"(a2), "r"(a3), "r"(b2), "r"(b3));
        }
    }

    int r0 = row0 + m0 + (lane >> 2);
    int cb = (lane & 3) * 2;
    float d0 = (r0 < NN) ? g_dinv[r0] : 0.f;
    float d1 = (r0 + 8 < NN) ? g_dinv[r0 + 8] : 0.f;
#pragma unroll
    for (int nt = 0; nt < 16; nt++) {
        if (r0 < NN)
            *(__half2*)&Y[(size_t)r0 * 128 + nt * 8 + cb] =
                __floats2half2_rn(acc[nt][0] * d0, acc[nt][1] * d0);
        if (r0 + 8 < NN)
            *(__half2*)&Y[(size_t)(r0 + 8) * 128 + nt * 8 + cb] =
                __floats2half2_rn(acc[nt][2] * d1, acc[nt][3] * d1);
    }
}

// ---------------- aggregation + folded-BN + ReLU (one warp per node) -------
// t' is pre-scaled by dinv[src] in the GEMM epilogue, so the inner loop is a
// pure gather+add: col[e] -> row gather -> fp32 accumulate. Final result is
// di * (t'[i] + sum_s t'[s]).
template <bool FINAL>
__global__ void __launch_bounds__(256) k_agg16(const float* __restrict__ beta,
                                               const float* __restrict__ Wl,
                                               const int* __restrict__ batch) {
    int warp = (blockIdx.x * blockDim.x + threadIdx.x) >> 5;
    int lane = threadIdx.x & 31;
    if (warp >= NN) return;
    int i = warp;

    const uint2* T = (const uint2*)g_t;   // 32 x uint2 (4 halves) per row
    float di = g_dinv[i];

    uint2 u = T[(size_t)i * 32 + lane];   // self term t'[i]
    float2 f0 = __half22float2(*(__half2*)&u.x);
    float2 f1 = __half22float2(*(__half2*)&u.y);
    float4 acc = make_float4(f0.x, f0.y, f1.x, f1.y);

    int e = g_rowptr[i];
    int e1 = g_rowptr[i + 1];

    for (; e + 4 <= e1; e += 4) {
        int s0 = __ldg(&g_col[e]);
        int s1 = __ldg(&g_col[e + 1]);
        int s2 = __ldg(&g_col[e + 2]);
        int s3 = __ldg(&g_col[e + 3]);
        uint2 v0 = T[(size_t)s0 * 32 + lane];
        uint2 v1 = T[(size_t)s1 * 32 + lane];
        uint2 v2 = T[(size_t)s2 * 32 + lane];
        uint2 v3 = T[(size_t)s3 * 32 + lane];
        float2 a, b;
        a = __half22float2(*(__half2*)&v0.x); b = __half22float2(*(__half2*)&v0.y);
        acc.x += a.x; acc.y += a.y; acc.z += b.x; acc.w += b.y;
        a = __half22float2(*(__half2*)&v1.x); b = __half22float2(*(__half2*)&v1.y);
        acc.x += a.x; acc.y += a.y; acc.z += b.x; acc.w += b.y;
        a = __half22float2(*(__half2*)&v2.x); b = __half22float2(*(__half2*)&v2.y);
        acc.x += a.x; acc.y += a.y; acc.z += b.x; acc.w += b.y;
        a = __half22float2(*(__half2*)&v3.x); b = __half22float2(*(__half2*)&v3.y);
        acc.x += a.x; acc.y += a.y; acc.z += b.x; acc.w += b.y;
    }
    for (; e < e1; ++e) {
        int s = __ldg(&g_col[e]);
        uint2 v = T[(size_t)s * 32 + lane];
        float2 a = __half22float2(*(__half2*)&v.x);
        float2 b = __half22float2(*(__half2*)&v.y);
        acc.x += a.x; acc.y += a.y; acc.z += b.x; acc.w += b.y;
    }

    float4 be = ((const float4*)beta)[lane];
    float4 y;
    y.x = fmaxf(0.f, fmaf(di, acc.x, be.x));
    y.y = fmaxf(0.f, fmaf(di, acc.y, be.y));
    y.z = fmaxf(0.f, fmaf(di, acc.z, be.z));
    y.w = fmaxf(0.f, fmaf(di, acc.w, be.w));

    if (!FINAL) {
        uint2 o;
        *(__half2*)&o.x = __floats2half2_rn(y.x, y.y);
        *(__half2*)&o.y = __floats2half2_rn(y.z, y.w);
        ((uint2*)g_h)[(size_t)i * 32 + lane] = o;
    } else {
        float4 wl = ((const float4*)Wl)[lane];
        float s = y.x * wl.x + y.y * wl.y + y.z * wl.z + y.w * wl.w;
#pragma unroll
        for (int off = 16; off > 0; off >>= 1)
            s += __shfl_xor_sync(0xFFFFFFFFu, s, off);
        if (lane == 0) atomicAdd(&g_gsum[batch[i]], s);
    }
}

__global__ void k_final(float* __restrict__ out, const float* __restrict__ bl) {
    int g = blockIdx.x * blockDim.x + threadIdx.x;
    if (g < GG) out[g] = g_gsum[g] / fmaxf((float)g_gcnt[g], 1.0f) + bl[0];
}

// ---------------- host launcher --------------------------------------------
extern "C" void kernel_launch(void* const* d_in, const int* in_sizes, int n_in,
                              void* d_out, int out_size) {
    const float* x     = (const float*)d_in[0];
    const int*   ei    = (const int*)d_in[1];
    const int*   batch = (const int*)d_in[2];
    const float* W1 = (const float*)d_in[3];
    const float* b1 = (const float*)d_in[4];
    const float* g1 = (const float*)d_in[5];
    const float* be1 = (const float*)d_in[6];
    const float* m1 = (const float*)d_in[7];
    const float* v1 = (const float*)d_in[8];
    const float* W2 = (const float*)d_in[9];
    const float* b2 = (const float*)d_in[10];
    const float* g2 = (const float*)d_in[11];
    const float* be2 = (const float*)d_in[12];
    const float* m2 = (const float*)d_in[13];
    const float* v2 = (const float*)d_in[14];
    const float* W3 = (const float*)d_in[15];
    const float* b3 = (const float*)d_in[16];
    const float* g3 = (const float*)d_in[17];
    const float* be3 = (const float*)d_in[18];
    const float* m3 = (const float*)d_in[19];
    const float* v3 = (const float*)d_in[20];
    const float* Wl = (const float*)d_in[21];
    const float* bl = (const float*)d_in[22];

    __half *t, *h, *Wh;
    float *beta;
    cudaGetSymbolAddress((void**)&t, g_t);
    cudaGetSymbolAddress((void**)&h, g_h);
    cudaGetSymbolAddress((void**)&Wh, g_Wh);
    cudaGetSymbolAddress((void**)&beta, g_beta);

    const int GEMM_SMEM = 2 * 128 * 136 * (int)sizeof(__half);   // 69632
    cudaFuncSetAttribute(k_gemm_tc<true>,  cudaFuncAttributeMaxDynamicSharedMemorySize, GEMM_SMEM);
    cudaFuncSetAttribute(k_gemm_tc<false>, cudaFuncAttributeMaxDynamicSharedMemorySize, GEMM_SMEM);

    const int TPB = 256;
    // ---- graph preprocessing (CSR by dst, dinv, per-graph counts)
    k_zero<<<(NN + TPB - 1) / TPB, TPB>>>();
    k_hist<<<(EE + TPB - 1) / TPB, TPB>>>(ei, batch);
    k_scan_local<<<NB, SCAN_B>>>();
    k_scan_part<<<1, 128>>>();
    k_scan_add<<<(NN + TPB) / TPB, TPB>>>();
    k_fill<<<(EE + TPB - 1) / TPB, TPB>>>(ei);

    // ---- weight prep: fold BN scale into W, convert to fp16 (all 3 layers)
    {
        dim3 grid(64, 3);
        k_prep_w<<<grid, 256>>>(W1, W2, W3, b1, b2, b3, g1, g2, g3,
                                be1, be2, be3, m1, m2, m3, v1, v2, v3);
    }

    const int GEMM_BLOCKS = (NN + 127) / 128;           // 782
    const int AGG_BLOCKS = (NN * 32 + TPB - 1) / TPB;   // 12500

    // ---- layer 1
    k_gemm_tc<true><<<GEMM_BLOCKS, 256, GEMM_SMEM>>>(x, Wh, t);
    k_agg16<false><<<AGG_BLOCKS, TPB>>>(beta, nullptr, nullptr);
    // ---- layer 2
    k_gemm_tc<false><<<GEMM_BLOCKS, 256, GEMM_SMEM>>>(h, Wh + HH * HH, t);
    k_agg16<false><<<AGG_BLOCKS, TPB>>>(beta + HH, nullptr, nullptr);
    // ---- layer 3 (fused mean-pool + linear head via per-node dot)
    k_gemm_tc<false><<<GEMM_BLOCKS, 256, GEMM_SMEM>>>(h, Wh + 2 * HH * HH, t);
    k_agg16<true><<<AGG_BLOCKS, TPB>>>(beta + 2 * HH, Wl, batch);

    k_final<<<(GG + TPB - 1) / TPB, TPB>>>((float*)d_out, bl);
}

// round 7
// speedup vs baseline: 1.2065x; 1.0024x over previous
#include <cuda_runtime.h>
#include <cuda_fp16.h>
#include <cstdint>

#define NN 100000
#define EE 1600000
#define HH 128
#define GG 512
#define BN_EPS 1e-5f
#define SCAN_B 1024
#define NB ((NN + SCAN_B - 1) / SCAN_B)   // 98 scan blocks

// ---------------- scratch (device globals: no allocation allowed) -----------
__device__ __half g_t[(size_t)NN * HH];   // GEMM output t' = dinv .* (h @ W') (fp16)
__device__ __half g_h[(size_t)NN * HH];   // activated hidden (fp16)
__device__ __half g_Wh[3 * HH * HH];      // BN-folded fp16 weights
__device__ float  g_beta[3 * HH];         // BN-folded shifts
__device__ float  g_dinv[NN];
__device__ int    g_deg[NN];
__device__ int    g_rowptr[NN + 1];
__device__ int    g_cursor[NN];
__device__ int    g_col[EE];
__device__ float  g_gsum[GG];
__device__ int    g_gcnt[GG];
__device__ int    g_part[NB];

__device__ __forceinline__ uint32_t s2u(const void* p) {
    return (uint32_t)__cvta_generic_to_shared(p);
}

// ---------------- preprocessing kernels ------------------------------------
__global__ void k_zero() {
    int i = blockIdx.x * blockDim.x + threadIdx.x;
    if (i < NN) g_deg[i] = 0;
    if (i < GG) { g_gsum[i] = 0.0f; g_gcnt[i] = 0; }
}

// degree histogram over dst + per-graph node counts (fused)
__global__ void k_hist(const int* __restrict__ ei, const int* __restrict__ batch) {
    int e = blockIdx.x * blockDim.x + threadIdx.x;
    if (e < EE) atomicAdd(&g_deg[ei[EE + e]], 1);
    if (e < NN) atomicAdd(&g_gcnt[batch[e]], 1);
}

__global__ void k_scan_local() {
    __shared__ int sh[SCAN_B];
    int tx = threadIdx.x;
    int i = blockIdx.x * SCAN_B + tx;
    int v = (i < NN) ? g_deg[i] : 0;
    if (i < NN) g_dinv[i] = rsqrtf((float)(v + 1));   // fused dinv (+1 self-loop)
    sh[tx] = v;
    __syncthreads();
    for (int off = 1; off < SCAN_B; off <<= 1) {
        int t = (tx >= off) ? sh[tx - off] : 0;
        __syncthreads();
        sh[tx] += t;
        __syncthreads();
    }
    if (i < NN) g_rowptr[i] = sh[tx] - v;        // exclusive
    if (tx == SCAN_B - 1) g_part[blockIdx.x] = sh[tx];
}

__global__ void k_scan_part() {
    __shared__ int sh[128];
    int tx = threadIdx.x;
    int v = (tx < NB) ? g_part[tx] : 0;
    sh[tx] = v;
    __syncthreads();
    for (int off = 1; off < 128; off <<= 1) {
        int t = (tx >= off) ? sh[tx - off] : 0;
        __syncthreads();
        sh[tx] += t;
        __syncthreads();
    }
    if (tx < NB) g_part[tx] = sh[tx] - v;        // exclusive block offsets
}

__global__ void k_scan_add() {
    int i = blockIdx.x * blockDim.x + threadIdx.x;
    if (i < NN) {
        int v = g_rowptr[i] + g_part[i >> 10];
        g_rowptr[i] = v;
        g_cursor[i] = v;
    }
    if (i == 0) g_rowptr[NN] = EE;
}

__global__ void k_fill(const int* __restrict__ ei) {
    int e = blockIdx.x * blockDim.x + threadIdx.x;
    if (e < EE) {
        int src = ei[e];
        int dst = ei[EE + e];
        int p = atomicAdd(&g_cursor[dst], 1);
        g_col[p] = src;
    }
}

// Fold BN scale into W columns (fp16) for all 3 layers, compute folded shifts.
__global__ void k_prep_w(const float* __restrict__ W1v, const float* __restrict__ W2v,
                         const float* __restrict__ W3v,
                         const float* __restrict__ b1v, const float* __restrict__ b2v,
                         const float* __restrict__ b3v,
                         const float* __restrict__ ga1, const float* __restrict__ ga2,
                         const float* __restrict__ ga3,
                         const float* __restrict__ be1, const float* __restrict__ be2,
                         const float* __restrict__ be3,
                         const float* __restrict__ m1v, const float* __restrict__ m2v,
                         const float* __restrict__ m3v,
                         const float* __restrict__ v1v, const float* __restrict__ v2v,
                         const float* __restrict__ v3v) {
    int layer = blockIdx.y;
    const float* W  = layer == 0 ? W1v : layer == 1 ? W2v : W3v;
    const float* b  = layer == 0 ? b1v : layer == 1 ? b2v : b3v;
    const float* ga = layer == 0 ? ga1 : layer == 1 ? ga2 : ga3;
    const float* be = layer == 0 ? be1 : layer == 1 ? be2 : be3;
    const float* m  = layer == 0 ? m1v : layer == 1 ? m2v : m3v;
    const float* v  = layer == 0 ? v1v : layer == 1 ? v2v : v3v;
    int idx = blockIdx.x * blockDim.x + threadIdx.x;
    if (idx < HH * HH) {
        int n = idx & (HH - 1);
        float alpha = ga[n] * rsqrtf(v[n] + BN_EPS);
        g_Wh[layer * HH * HH + idx] = __float2half(W[idx] * alpha);
    }
    if (idx < HH) {
        float alpha = ga[idx] * rsqrtf(v[idx] + BN_EPS);
        g_beta[layer * HH + idx] = (b[idx] - m[idx]) * alpha + be[idx];
    }
}

// ---------------- fp16 tensor-core GEMM + dinv prescale epilogue -----------
// Y[i,:] = dinv[i] * (X[i,:] @ W)   -> agg inner loop needs NO per-edge dinv.
template <bool F32IN>
__global__ void __launch_bounds__(256) k_gemm_tc(const void* __restrict__ Xv,
                                                 const __half* __restrict__ W,
                                                 __half* __restrict__ Y) {
    extern __shared__ __half sh[];
    __half* As = sh;               // 128 x 136
    __half* Ws = sh + 128 * 136;   // 128 x 136 (row = k, cols = n)

    int tid = threadIdx.x;
    int row0 = blockIdx.x * 128;

    // load W tile (fp16, 128x128)
    const uint4* Wg = (const uint4*)W;
#pragma unroll
    for (int i = 0; i < 8; i++) {
        int idx = i * 256 + tid;          // uint4 = 8 halves; 2048 total
        int r = idx >> 4, c = (idx & 15) * 8;
        *(uint4*)&Ws[r * 136 + c] = Wg[idx];
    }
    // load A tile
    if (F32IN) {
        const float4* Xg = (const float4*)Xv;
#pragma unroll
        for (int i = 0; i < 16; i++) {
            int idx = i * 256 + tid;      // float4; 4096 total
            int r = idx >> 5, c = (idx & 31) * 4;
            float4 v = make_float4(0.f, 0.f, 0.f, 0.f);
            if (row0 + r < NN) v = Xg[(size_t)(row0 + r) * 32 + (idx & 31)];
            *(__half2*)&As[r * 136 + c]     = __floats2half2_rn(v.x, v.y);
            *(__half2*)&As[r * 136 + c + 2] = __floats2half2_rn(v.z, v.w);
        }
    } else {
        const uint4* Xg = (const uint4*)Xv;
#pragma unroll
        for (int i = 0; i < 8; i++) {
            int idx = i * 256 + tid;      // uint4 = 8 halves; 2048 total
            int r = idx >> 4, c = (idx & 15) * 8;
            uint4 v = make_uint4(0, 0, 0, 0);
            if (row0 + r < NN) v = Xg[(size_t)(row0 + r) * 16 + (idx & 15)];
            *(uint4*)&As[r * 136 + c] = v;
        }
    }
    __syncthreads();

    int wid = tid >> 5, lane = tid & 31;
    int m0 = wid * 16;

    float acc[16][4];
#pragma unroll
    for (int nt = 0; nt < 16; nt++)
#pragma unroll
        for (int c = 0; c < 4; c++) acc[nt][c] = 0.f;

#pragma unroll
    for (int ks = 0; ks < 8; ks++) {
        uint32_t a0, a1, a2, a3;
        uint32_t aaddr = s2u(&As[(m0 + (lane & 15)) * 136 + ks * 16 + (lane >> 4) * 8]);
        asm volatile("ldmatrix.sync.aligned.m8n8.x4.shared.b16 {%0,%1,%2,%3}, [%4];"
                     : "=r"(a0), "=r"(a1), "=r"(a2), "=r"(a3) : "r"(aaddr));
        // B fragments: one x4.trans per 16-column group (covers 2 n8 tiles)
#pragma unroll
        for (int ng = 0; ng < 8; ng++) {
            uint32_t b0, b1, b2, b3;
            uint32_t baddr = s2u(&Ws[(ks * 16 + (lane & 15)) * 136 +
                                     ng * 16 + (lane >> 4) * 8]);
            asm volatile("ldmatrix.sync.aligned.m8n8.x4.trans.shared.b16 {%0,%1,%2,%3}, [%4];"
                         : "=r"(b0), "=r"(b1), "=r"(b2), "=r"(b3) : "r"(baddr));
            int nt = ng * 2;
            asm volatile(
                "mma.sync.aligned.m16n8k16.row.col.f32.f16.f16.f32 "
                "{%0,%1,%2,%3}, {%4,%5,%6,%7}, {%8,%9}, {%0,%1,%2,%3};"
                : "+f"(acc[nt][0]), "+f"(acc[nt][1]), "+f"(acc[nt][2]), "+f"(acc[nt][3])
                : "r"(a0), "r"(a1), "r"(a2), "r"(a3), "r"(b0), "r"(b1));
            asm volatile(
                "mma.sync.aligned.m16n8k16.row.col.f32.f16.f16.f32 "
                "{%0,%1,%2,%3}, {%4,%5,%6,%7}, {%8,%9}, {%0,%1,%2,%3};"
                : "+f"(acc[nt + 1][0]), "+f"(acc[nt + 1][1]), "+f"(acc[nt + 1][2]), "+f"(acc[nt + 1][3])
                : "r"(a0), "r"(a1), "r"(a2), "r"(a3), "r"(b2), "r"(b3));
        }
    }

    int r0 = row0 + m0 + (lane >> 2);
    int cb = (lane & 3) * 2;
    float d0 = (r0 < NN) ? g_dinv[r0] : 0.f;
    float d1 = (r0 + 8 < NN) ? g_dinv[r0 + 8] : 0.f;
#pragma unroll
    for (int nt = 0; nt < 16; nt++) {
        if (r0 < NN)
            *(__half2*)&Y[(size_t)r0 * 128 + nt * 8 + cb] =
                __floats2half2_rn(acc[nt][0] * d0, acc[nt][1] * d0);
        if (r0 + 8 < NN)
            *(__half2*)&Y[(size_t)(r0 + 8) * 128 + nt * 8 + cb] =
                __floats2half2_rn(acc[nt][2] * d1, acc[nt][3] * d1);
    }
}

// ---------------- aggregation + folded-BN + ReLU (one warp per node) -------
// t' is pre-scaled by dinv[src]; inner loop is pure gather+add, unrolled x8.
template <bool FINAL>
__global__ void __launch_bounds__(256) k_agg16(const float* __restrict__ beta,
                                               const float* __restrict__ Wl,
                                               const int* __restrict__ batch) {
    int warp = (blockIdx.x * blockDim.x + threadIdx.x) >> 5;
    int lane = threadIdx.x & 31;
    if (warp >= NN) return;
    int i = warp;

    const uint2* T = (const uint2*)g_t;   // 32 x uint2 (4 halves) per row
    float di = g_dinv[i];

    uint2 u = T[(size_t)i * 32 + lane];   // self term t'[i]
    float2 f0 = __half22float2(*(__half2*)&u.x);
    float2 f1 = __half22float2(*(__half2*)&u.y);
    float4 acc = make_float4(f0.x, f0.y, f1.x, f1.y);

    int e = g_rowptr[i];
    int e1 = g_rowptr[i + 1];

    for (; e + 8 <= e1; e += 8) {
        int s[8];
        uint2 v[8];
#pragma unroll
        for (int j = 0; j < 8; j++) s[j] = __ldg(&g_col[e + j]);
#pragma unroll
        for (int j = 0; j < 8; j++) v[j] = T[(size_t)s[j] * 32 + lane];
#pragma unroll
        for (int j = 0; j < 8; j++) {
            float2 a = __half22float2(*(__half2*)&v[j].x);
            float2 b = __half22float2(*(__half2*)&v[j].y);
            acc.x += a.x; acc.y += a.y; acc.z += b.x; acc.w += b.y;
        }
    }
    for (; e + 4 <= e1; e += 4) {
        int s[4];
        uint2 v[4];
#pragma unroll
        for (int j = 0; j < 4; j++) s[j] = __ldg(&g_col[e + j]);
#pragma unroll
        for (int j = 0; j < 4; j++) v[j] = T[(size_t)s[j] * 32 + lane];
#pragma unroll
        for (int j = 0; j < 4; j++) {
            float2 a = __half22float2(*(__half2*)&v[j].x);
            float2 b = __half22float2(*(__half2*)&v[j].y);
            acc.x += a.x; acc.y += a.y; acc.z += b.x; acc.w += b.y;
        }
    }
    for (; e < e1; ++e) {
        int s = __ldg(&g_col[e]);
        uint2 v = T[(size_t)s * 32 + lane];
        float2 a = __half22float2(*(__half2*)&v.x);
        float2 b = __half22float2(*(__half2*)&v.y);
        acc.x += a.x; acc.y += a.y; acc.z += b.x; acc.w += b.y;
    }

    float4 be = ((const float4*)beta)[lane];
    float4 y;
    y.x = fmaxf(0.f, fmaf(di, acc.x, be.x));
    y.y = fmaxf(0.f, fmaf(di, acc.y, be.y));
    y.z = fmaxf(0.f, fmaf(di, acc.z, be.z));
    y.w = fmaxf(0.f, fmaf(di, acc.w, be.w));

    if (!FINAL) {
        uint2 o;
        *(__half2*)&o.x = __floats2half2_rn(y.x, y.y);
        *(__half2*)&o.y = __floats2half2_rn(y.z, y.w);
        ((uint2*)g_h)[(size_t)i * 32 + lane] = o;
    } else {
        float4 wl = ((const float4*)Wl)[lane];
        float s = y.x * wl.x + y.y * wl.y + y.z * wl.z + y.w * wl.w;
#pragma unroll
        for (int off = 16; off > 0; off >>= 1)
            s += __shfl_xor_sync(0xFFFFFFFFu, s, off);
        if (lane == 0) atomicAdd(&g_gsum[batch[i]], s);
    }
}

__global__ void k_final(float* __restrict__ out, const float* __restrict__ bl) {
    int g = blockIdx.x * blockDim.x + threadIdx.x;
    if (g < GG) out[g] = g_gsum[g] / fmaxf((float)g_gcnt[g], 1.0f) + bl[0];
}

// ---------------- host launcher --------------------------------------------
extern "C" void kernel_launch(void* const* d_in, const int* in_sizes, int n_in,
                              void* d_out, int out_size) {
    const float* x     = (const float*)d_in[0];
    const int*   ei    = (const int*)d_in[1];
    const int*   batch = (const int*)d_in[2];
    const float* W1 = (const float*)d_in[3];
    const float* b1 = (const float*)d_in[4];
    const float* g1 = (const float*)d_in[5];
    const float* be1 = (const float*)d_in[6];
    const float* m1 = (const float*)d_in[7];
    const float* v1 = (const float*)d_in[8];
    const float* W2 = (const float*)d_in[9];
    const float* b2 = (const float*)d_in[10];
    const float* g2 = (const float*)d_in[11];
    const float* be2 = (const float*)d_in[12];
    const float* m2 = (const float*)d_in[13];
    const float* v2 = (const float*)d_in[14];
    const float* W3 = (const float*)d_in[15];
    const float* b3 = (const float*)d_in[16];
    const float* g3 = (const float*)d_in[17];
    const float* be3 = (const float*)d_in[18];
    const float* m3 = (const float*)d_in[19];
    const float* v3 = (const float*)d_in[20];
    const float* Wl = (const float*)d_in[21];
    const float* bl = (const float*)d_in[22];

    __half *t, *h, *Wh;
    float *beta;
    cudaGetSymbolAddress((void**)&t, g_t);
    cudaGetSymbolAddress((void**)&h, g_h);
    cudaGetSymbolAddress((void**)&Wh, g_Wh);
    cudaGetSymbolAddress((void**)&beta, g_beta);

    const int GEMM_SMEM = 2 * 128 * 136 * (int)sizeof(__half);   // 69632
    cudaFuncSetAttribute(k_gemm_tc<true>,  cudaFuncAttributeMaxDynamicSharedMemorySize, GEMM_SMEM);
    cudaFuncSetAttribute(k_gemm_tc<false>, cudaFuncAttributeMaxDynamicSharedMemorySize, GEMM_SMEM);

    // side stream + events for capture-fork overlap (created once, reused;
    // creation is host-side resource setup, no device memory involved)
    static cudaStream_t s1 = nullptr;
    static cudaEvent_t evStart = nullptr, evDinv = nullptr, evG1 = nullptr;
    if (s1 == nullptr) {
        cudaStreamCreateWithFlags(&s1, cudaStreamNonBlocking);
        cudaEventCreateWithFlags(&evStart, cudaEventDisableTiming);
        cudaEventCreateWithFlags(&evDinv, cudaEventDisableTiming);
        cudaEventCreateWithFlags(&evG1, cudaEventDisableTiming);
    }

    const int TPB = 256;
    const int GEMM_BLOCKS = (NN + 127) / 128;           // 782
    const int AGG_BLOCKS = (NN * 32 + TPB - 1) / TPB;   // 12500

    // ---- fork: side stream handles weight prep (input-only dependency)
    cudaEventRecord(evStart, 0);
    cudaStreamWaitEvent(s1, evStart, 0);
    {
        dim3 grid(64, 3);
        k_prep_w<<<grid, 256, 0, s1>>>(W1, W2, W3, b1, b2, b3, g1, g2, g3,
                                       be1, be2, be3, m1, m2, m3, v1, v2, v3);
    }

    // ---- main stream: graph preprocessing
    k_zero<<<(NN + TPB - 1) / TPB, TPB>>>();
    k_hist<<<(EE + TPB - 1) / TPB, TPB>>>(ei, batch);
    k_scan_local<<<NB, SCAN_B>>>();                     // produces dinv
    cudaEventRecord(evDinv, 0);
    k_scan_part<<<1, 128>>>();
    k_scan_add<<<(NN + TPB) / TPB, TPB>>>();
    k_fill<<<(EE + TPB - 1) / TPB, TPB>>>(ei);

    // ---- side stream: gemm1 (needs Wh + dinv), overlaps scan/fill
    cudaStreamWaitEvent(s1, evDinv, 0);
    k_gemm_tc<true><<<GEMM_BLOCKS, 256, GEMM_SMEM, s1>>>(x, Wh, t);
    cudaEventRecord(evG1, s1);

    // ---- join, then layer 1 aggregation onward (serial on main stream)
    cudaStreamWaitEvent(0, evG1, 0);
    k_agg16<false><<<AGG_BLOCKS, TPB>>>(beta, nullptr, nullptr);
    // ---- layer 2
    k_gemm_tc<false><<<GEMM_BLOCKS, 256, GEMM_SMEM>>>(h, Wh + HH * HH, t);
    k_agg16<false><<<AGG_BLOCKS, TPB>>>(beta + HH, nullptr, nullptr);
    // ---- layer 3 (fused mean-pool + linear head via per-node dot)
    k_gemm_tc<false><<<GEMM_BLOCKS, 256, GEMM_SMEM>>>(h, Wh + 2 * HH * HH, t);
    k_agg16<true><<<AGG_BLOCKS, TPB>>>(beta + 2 * HH, Wl, batch);

    k_final<<<(GG + TPB - 1) / TPB, TPB>>>((float*)d_out, bl);
}

// round 9
// speedup vs baseline: 1.3136x; 1.0887x over previous
#include <cuda_runtime.h>
#include <cuda_fp16.h>
#include <cstdint>

#define NN 100000
#define EE 1600000
#define HH 128
#define GG 512
#define BN_EPS 1e-5f
#define SCAN_B 1024
#define NB ((NN + SCAN_B - 1) / SCAN_B)   // 98 scan blocks

// ---------------- scratch (device globals: no allocation allowed) -----------
__device__ __half g_t[(size_t)NN * HH];   // GEMM output t' = dinv .* (h @ W') (fp16)
__device__ __half g_h[(size_t)NN * HH];   // activated hidden (fp16)
__device__ __half g_Wh[3 * HH * HH];      // BN-folded fp16 weights
__device__ float  g_beta[3 * HH];         // BN-folded shifts
__device__ float  g_dinv[NN];
__device__ int    g_deg[NN];
__device__ int    g_rowptr[NN + 1];
__device__ int    g_cursor[NN];
__device__ int    g_col[EE];
__device__ float  g_gsum[GG];
__device__ int    g_gcnt[GG];
__device__ int    g_part[NB];

__device__ __forceinline__ uint32_t s2u(const void* p) {
    return (uint32_t)__cvta_generic_to_shared(p);
}

// ---------------- preprocessing kernels ------------------------------------
__global__ void k_zero() {
    int i = blockIdx.x * blockDim.x + threadIdx.x;
    if (i < NN) g_deg[i] = 0;
    if (i < GG) { g_gsum[i] = 0.0f; g_gcnt[i] = 0; }
}

__global__ void k_hist(const int* __restrict__ ei, const int* __restrict__ batch) {
    int e = blockIdx.x * blockDim.x + threadIdx.x;
    if (e < EE) atomicAdd(&g_deg[ei[EE + e]], 1);
    if (e < NN) atomicAdd(&g_gcnt[batch[e]], 1);
}

__global__ void k_scan_local() {
    __shared__ int sh[SCAN_B];
    int tx = threadIdx.x;
    int i = blockIdx.x * SCAN_B + tx;
    int v = (i < NN) ? g_deg[i] : 0;
    if (i < NN) g_dinv[i] = rsqrtf((float)(v + 1));   // fused dinv (+1 self-loop)
    sh[tx] = v;
    __syncthreads();
    for (int off = 1; off < SCAN_B; off <<= 1) {
        int t = (tx >= off) ? sh[tx - off] : 0;
        __syncthreads();
        sh[tx] += t;
        __syncthreads();
    }
    if (i < NN) g_rowptr[i] = sh[tx] - v;        // exclusive
    if (tx == SCAN_B - 1) g_part[blockIdx.x] = sh[tx];
}

__global__ void k_scan_part() {
    __shared__ int sh[128];
    int tx = threadIdx.x;
    int v = (tx < NB) ? g_part[tx] : 0;
    sh[tx] = v;
    __syncthreads();
    for (int off = 1; off < 128; off <<= 1) {
        int t = (tx >= off) ? sh[tx - off] : 0;
        __syncthreads();
        sh[tx] += t;
        __syncthreads();
    }
    if (tx < NB) g_part[tx] = sh[tx] - v;        // exclusive block offsets
}

__global__ void k_scan_add() {
    int i = blockIdx.x * blockDim.x + threadIdx.x;
    if (i < NN) {
        int v = g_rowptr[i] + g_part[i >> 10];
        g_rowptr[i] = v;
        g_cursor[i] = v;
    }
    if (i == 0) g_rowptr[NN] = EE;
}

__global__ void k_fill(const int* __restrict__ ei) {
    int e = blockIdx.x * blockDim.x + threadIdx.x;
    if (e < EE) {
        int src = ei[e];
        int dst = ei[EE + e];
        int p = atomicAdd(&g_cursor[dst], 1);
        g_col[p] = src;
    }
}

// Fold BN scale into W columns (fp16) for all 3 layers, compute folded shifts.
__global__ void k_prep_w(const float* __restrict__ W1v, const float* __restrict__ W2v,
                         const float* __restrict__ W3v,
                         const float* __restrict__ b1v, const float* __restrict__ b2v,
                         const float* __restrict__ b3v,
                         const float* __restrict__ ga1, const float* __restrict__ ga2,
                         const float* __restrict__ ga3,
                         const float* __restrict__ be1, const float* __restrict__ be2,
                         const float* __restrict__ be3,
                         const float* __restrict__ m1v, const float* __restrict__ m2v,
                         const float* __restrict__ m3v,
                         const float* __restrict__ v1v, const float* __restrict__ v2v,
                         const float* __restrict__ v3v) {
    int layer = blockIdx.y;
    const float* W  = layer == 0 ? W1v : layer == 1 ? W2v : W3v;
    const float* b  = layer == 0 ? b1v : layer == 1 ? b2v : b3v;
    const float* ga = layer == 0 ? ga1 : layer == 1 ? ga2 : ga3;
    const float* be = layer == 0 ? be1 : layer == 1 ? be2 : be3;
    const float* m  = layer == 0 ? m1v : layer == 1 ? m2v : m3v;
    const float* v  = layer == 0 ? v1v : layer == 1 ? v2v : v3v;
    int idx = blockIdx.x * blockDim.x + threadIdx.x;
    if (idx < HH * HH) {
        int n = idx & (HH - 1);
        float alpha = ga[n] * rsqrtf(v[n] + BN_EPS);
        g_Wh[layer * HH * HH + idx] = __float2half(W[idx] * alpha);
    }
    if (idx < HH) {
        float alpha = ga[idx] * rsqrtf(v[idx] + BN_EPS);
        g_beta[layer * HH + idx] = (b[idx] - m[idx]) * alpha + be[idx];
    }
}

// ---------------- fp16 tensor-core GEMM + dinv prescale epilogue -----------
// Y[i,:] = dinv[i] * (X[i,:] @ W).
// F32IN: bulk sync loads (with f32->f16 convert). !F32IN: cp.async 2-stage
// K-split. Stage h provides: A k-columns [h*64,h*64+64) (byte-half of each
// A row) and W k-ROWS [h*64,h*64+64) (full 256B rows). Compute of stage 0
// overlaps the stage-1 copies.
template <bool F32IN>
__global__ void __launch_bounds__(256) k_gemm_tc(const void* __restrict__ Xv,
                                                 const __half* __restrict__ W,
                                                 __half* __restrict__ Y) {
    extern __shared__ __half sh[];
    __half* As = sh;               // 128 x 136 (272 B pitch)
    __half* Ws = sh + 128 * 136;   // 128 x 136 (row = k, cols = n)

    int tid = threadIdx.x;
    int row0 = blockIdx.x * 128;

    if (F32IN) {
        const uint4* Wg = (const uint4*)W;
#pragma unroll
        for (int i = 0; i < 8; i++) {
            int idx = i * 256 + tid;          // uint4 = 8 halves; 2048 total
            int r = idx >> 4, c = (idx & 15) * 8;
            *(uint4*)&Ws[r * 136 + c] = Wg[idx];
        }
        const float4* Xg = (const float4*)Xv;
#pragma unroll
        for (int i = 0; i < 16; i++) {
            int idx = i * 256 + tid;      // float4; 4096 total
            int r = idx >> 5, c = (idx & 31) * 4;
            float4 v = make_float4(0.f, 0.f, 0.f, 0.f);
            if (row0 + r < NN) v = Xg[(size_t)(row0 + r) * 32 + (idx & 31)];
            *(__half2*)&As[r * 136 + c]     = __floats2half2_rn(v.x, v.y);
            *(__half2*)&As[r * 136 + c + 2] = __floats2half2_rn(v.z, v.w);
        }
        __syncthreads();
    } else {
        const char* Ag = (const char*)Xv;     // 256 B per row (k bytes)
        const char* Wg = (const char*)W;      // 256 B per row (row = k, bytes = n)
#pragma unroll
        for (int h = 0; h < 2; h++) {
            // A: all 128 rows, byte range [h*128, h*128+128) = k cols [h*64,..)
#pragma unroll
            for (int i = 0; i < 4; i++) {
                int idx = i * 256 + tid;      // 1024 chunks
                int r = idx >> 3, ch = idx & 7;
                uint32_t saddr = s2u(&As[0]) + r * 272 + h * 128 + ch * 16;
                const char* gaddr = Ag + (size_t)(row0 + r) * 256 + h * 128 + ch * 16;
                int sz = (row0 + r < NN) ? 16 : 0;
                asm volatile("cp.async.cg.shared.global [%0], [%1], 16, %2;"
                             :: "r"(saddr), "l"(gaddr), "r"(sz));
            }
            // W: k rows [h*64, h*64+64), full 256 B each (all n columns)
#pragma unroll
            for (int i = 0; i < 4; i++) {
                int idx = i * 256 + tid;      // 1024 chunks
                int r = h * 64 + (idx >> 4);  // 64 rows x 16 chunks
                int ch = idx & 15;
                uint32_t saddr = s2u(&Ws[0]) + r * 272 + ch * 16;
                const char* gaddr = Wg + (size_t)r * 256 + ch * 16;
                asm volatile("cp.async.cg.shared.global [%0], [%1], 16;"
                             :: "r"(saddr), "l"(gaddr));
            }
            asm volatile("cp.async.commit_group;");
        }
    }

    int wid = tid >> 5, lane = tid & 31;
    int m0 = wid * 16;

    float acc[16][4];
#pragma unroll
    for (int nt = 0; nt < 16; nt++)
#pragma unroll
        for (int c = 0; c < 4; c++) acc[nt][c] = 0.f;

#pragma unroll
    for (int h = 0; h < 2; h++) {
        if (!F32IN) {
            if (h == 0) { asm volatile("cp.async.wait_group 1;"); }
            else        { asm volatile("cp.async.wait_group 0;"); }
            __syncthreads();
        }
#pragma unroll
        for (int ksl = 0; ksl < 4; ksl++) {
            int ks = h * 4 + ksl;
            uint32_t a0, a1, a2, a3;
            uint32_t aaddr = s2u(&As[(m0 + (lane & 15)) * 136 + ks * 16 + (lane >> 4) * 8]);
            asm volatile("ldmatrix.sync.aligned.m8n8.x4.shared.b16 {%0,%1,%2,%3}, [%4];"
                         : "=r"(a0), "=r"(a1), "=r"(a2), "=r"(a3) : "r"(aaddr));
#pragma unroll
            for (int ng = 0; ng < 8; ng++) {
                uint32_t b0, b1, b2, b3;
                uint32_t baddr = s2u(&Ws[(ks * 16 + (lane & 15)) * 136 +
                                         ng * 16 + (lane >> 4) * 8]);
                asm volatile("ldmatrix.sync.aligned.m8n8.x4.trans.shared.b16 {%0,%1,%2,%3}, [%4];"
                             : "=r"(b0), "=r"(b1), "=r"(b2), "=r"(b3) : "r"(baddr));
                int nt = ng * 2;
                asm volatile(
                    "mma.sync.aligned.m16n8k16.row.col.f32.f16.f16.f32 "
                    "{%0,%1,%2,%3}, {%4,%5,%6,%7}, {%8,%9}, {%0,%1,%2,%3};"
                    : "+f"(acc[nt][0]), "+f"(acc[nt][1]), "+f"(acc[nt][2]), "+f"(acc[nt][3])
                    : "r"(a0), "r"(a1), "r"(a2), "r"(a3), "r"(b0), "r"(b1));
                asm volatile(
                    "mma.sync.aligned.m16n8k16.row.col.f32.f16.f16.f32 "
                    "{%0,%1,%2,%3}, {%4,%5,%6,%7}, {%8,%9}, {%0,%1,%2,%3};"
                    : "+f"(acc[nt + 1][0]), "+f"(acc[nt + 1][1]), "+f"(acc[nt + 1][2]), "+f"(acc[nt + 1][3])
                    : "r"(a0), "r"(a1), "r"(a2), "r"(a3), "r"(b2), "r"(b3));
            }
        }
    }

    int r0 = row0 + m0 + (lane >> 2);
    int cb = (lane & 3) * 2;
    float d0 = (r0 < NN) ? g_dinv[r0] : 0.f;
    float d1 = (r0 + 8 < NN) ? g_dinv[r0 + 8] : 0.f;
#pragma unroll
    for (int nt = 0; nt < 16; nt++) {
        if (r0 < NN)
            *(__half2*)&Y[(size_t)r0 * 128 + nt * 8 + cb] =
                __floats2half2_rn(acc[nt][0] * d0, acc[nt][1] * d0);
        if (r0 + 8 < NN)
            *(__half2*)&Y[(size_t)(r0 + 8) * 128 + nt * 8 + cb] =
                __floats2half2_rn(acc[nt][2] * d1, acc[nt][3] * d1);
    }
}

// ---------------- aggregation + folded-BN + ReLU (2 nodes per warp) --------
// 16 lanes x uint4 (LDG.128) per node row: half the load instructions of the
// 32-lane uint2 layout. t' pre-scaled by dinv[src]; pure gather+add.
template <bool FINAL>
__global__ void __launch_bounds__(256) k_agg16(const float* __restrict__ beta,
                                               const float* __restrict__ Wl,
                                               const int* __restrict__ batch) {
    int warp = (blockIdx.x * blockDim.x + threadIdx.x) >> 5;
    int lane = threadIdx.x & 31;
    int half = lane >> 4;
    int sub = lane & 15;
    int node = warp * 2 + half;
    if (node >= NN) return;

    const uint4* T = (const uint4*)g_t;   // 16 x uint4 (8 halves) per row
    float di = g_dinv[node];

    float acc[8];
    {
        uint4 u = T[(size_t)node * 16 + sub];   // self term t'[i]
        const __half2* p = (const __half2*)&u;
#pragma unroll
        for (int q = 0; q < 4; q++) {
            float2 f = __half22float2(p[q]);
            acc[q * 2] = f.x; acc[q * 2 + 1] = f.y;
        }
    }

    int e = g_rowptr[node];
    int e1 = g_rowptr[node + 1];

    for (; e + 8 <= e1; e += 8) {
        int s[8];
        uint4 v[8];
#pragma unroll
        for (int j = 0; j < 8; j++) s[j] = __ldg(&g_col[e + j]);
#pragma unroll
        for (int j = 0; j < 8; j++) v[j] = T[(size_t)s[j] * 16 + sub];
#pragma unroll
        for (int j = 0; j < 8; j++) {
            const __half2* p = (const __half2*)&v[j];
#pragma unroll
            for (int q = 0; q < 4; q++) {
                float2 f = __half22float2(p[q]);
                acc[q * 2] += f.x; acc[q * 2 + 1] += f.y;
            }
        }
    }
    for (; e + 4 <= e1; e += 4) {
        int s[4];
        uint4 v[4];
#pragma unroll
        for (int j = 0; j < 4; j++) s[j] = __ldg(&g_col[e + j]);
#pragma unroll
        for (int j = 0; j < 4; j++) v[j] = T[(size_t)s[j] * 16 + sub];
#pragma unroll
        for (int j = 0; j < 4; j++) {
            const __half2* p = (const __half2*)&v[j];
#pragma unroll
            for (int q = 0; q < 4; q++) {
                float2 f = __half22float2(p[q]);
                acc[q * 2] += f.x; acc[q * 2 + 1] += f.y;
            }
        }
    }
    for (; e < e1; ++e) {
        int s = __ldg(&g_col[e]);
        uint4 v = T[(size_t)s * 16 + sub];
        const __half2* p = (const __half2*)&v;
#pragma unroll
        for (int q = 0; q < 4; q++) {
            float2 f = __half22float2(p[q]);
            acc[q * 2] += f.x; acc[q * 2 + 1] += f.y;
        }
    }

    float4 be0 = ((const float4*)beta)[sub * 2];
    float4 be1v = ((const float4*)beta)[sub * 2 + 1];
    float y[8];
    y[0] = fmaxf(0.f, fmaf(di, acc[0], be0.x));
    y[1] = fmaxf(0.f, fmaf(di, acc[1], be0.y));
    y[2] = fmaxf(0.f, fmaf(di, acc[2], be0.z));
    y[3] = fmaxf(0.f, fmaf(di, acc[3], be0.w));
    y[4] = fmaxf(0.f, fmaf(di, acc[4], be1v.x));
    y[5] = fmaxf(0.f, fmaf(di, acc[5], be1v.y));
    y[6] = fmaxf(0.f, fmaf(di, acc[6], be1v.z));
    y[7] = fmaxf(0.f, fmaf(di, acc[7], be1v.w));

    if (!FINAL) {
        uint4 o;
        __half2* p = (__half2*)&o;
        p[0] = __floats2half2_rn(y[0], y[1]);
        p[1] = __floats2half2_rn(y[2], y[3]);
        p[2] = __floats2half2_rn(y[4], y[5]);
        p[3] = __floats2half2_rn(y[6], y[7]);
        ((uint4*)g_h)[(size_t)node * 16 + sub] = o;
    } else {
        float4 wl0 = ((const float4*)Wl)[sub * 2];
        float4 wl1 = ((const float4*)Wl)[sub * 2 + 1];
        float s = y[0] * wl0.x + y[1] * wl0.y + y[2] * wl0.z + y[3] * wl0.w +
                  y[4] * wl1.x + y[5] * wl1.y + y[6] * wl1.z + y[7] * wl1.w;
        unsigned mask = half ? 0xFFFF0000u : 0x0000FFFFu;
#pragma unroll
        for (int off = 8; off > 0; off >>= 1)
            s += __shfl_xor_sync(mask, s, off);
        if (sub == 0) atomicAdd(&g_gsum[batch[node]], s);
    }
}

__global__ void k_final(float* __restrict__ out, const float* __restrict__ bl) {
    int g = blockIdx.x * blockDim.x + threadIdx.x;
    if (g < GG) out[g] = g_gsum[g] / fmaxf((float)g_gcnt[g], 1.0f) + bl[0];
}

// ---------------- host launcher --------------------------------------------
extern "C" void kernel_launch(void* const* d_in, const int* in_sizes, int n_in,
                              void* d_out, int out_size) {
    const float* x     = (const float*)d_in[0];
    const int*   ei    = (const int*)d_in[1];
    const int*   batch = (const int*)d_in[2];
    const float* W1 = (const float*)d_in[3];
    const float* b1 = (const float*)d_in[4];
    const float* g1 = (const float*)d_in[5];
    const float* be1 = (const float*)d_in[6];
    const float* m1 = (const float*)d_in[7];
    const float* v1 = (const float*)d_in[8];
    const float* W2 = (const float*)d_in[9];
    const float* b2 = (const float*)d_in[10];
    const float* g2 = (const float*)d_in[11];
    const float* be2 = (const float*)d_in[12];
    const float* m2 = (const float*)d_in[13];
    const float* v2 = (const float*)d_in[14];
    const float* W3 = (const float*)d_in[15];
    const float* b3 = (const float*)d_in[16];
    const float* g3 = (const float*)d_in[17];
    const float* be3 = (const float*)d_in[18];
    const float* m3 = (const float*)d_in[19];
    const float* v3 = (const float*)d_in[20];
    const float* Wl = (const float*)d_in[21];
    const float* bl = (const float*)d_in[22];

    __half *t, *h, *Wh;
    float *beta;
    cudaGetSymbolAddress((void**)&t, g_t);
    cudaGetSymbolAddress((void**)&h, g_h);
    cudaGetSymbolAddress((void**)&Wh, g_Wh);
    cudaGetSymbolAddress((void**)&beta, g_beta);

    const int GEMM_SMEM = 2 * 128 * 136 * (int)sizeof(__half);   // 69632
    cudaFuncSetAttribute(k_gemm_tc<true>,  cudaFuncAttributeMaxDynamicSharedMemorySize, GEMM_SMEM);
    cudaFuncSetAttribute(k_gemm_tc<false>, cudaFuncAttributeMaxDynamicSharedMemorySize, GEMM_SMEM);

    static cudaStream_t s1 = nullptr;
    static cudaEvent_t evStart = nullptr, evDinv = nullptr, evG1 = nullptr;
    if (s1 == nullptr) {
        cudaStreamCreateWithFlags(&s1, cudaStreamNonBlocking);
        cudaEventCreateWithFlags(&evStart, cudaEventDisableTiming);
        cudaEventCreateWithFlags(&evDinv, cudaEventDisableTiming);
        cudaEventCreateWithFlags(&evG1, cudaEventDisableTiming);
    }

    const int TPB = 256;
    const int GEMM_BLOCKS = (NN + 127) / 128;                 // 782
    const int AGG_BLOCKS = ((NN + 1) / 2 * 32 + TPB - 1) / TPB;  // 6250

    // ---- fork: side stream handles weight prep (input-only dependency)
    cudaEventRecord(evStart, 0);
    cudaStreamWaitEvent(s1, evStart, 0);
    {
        dim3 grid(64, 3);
        k_prep_w<<<grid, 256, 0, s1>>>(W1, W2, W3, b1, b2, b3, g1, g2, g3,
                                       be1, be2, be3, m1, m2, m3, v1, v2, v3);
    }

    // ---- main stream: graph preprocessing
    k_zero<<<(NN + TPB - 1) / TPB, TPB>>>();
    k_hist<<<(EE + TPB - 1) / TPB, TPB>>>(ei, batch);
    k_scan_local<<<NB, SCAN_B>>>();                     // produces dinv
    cudaEventRecord(evDinv, 0);
    k_scan_part<<<1, 128>>>();
    k_scan_add<<<(NN + TPB) / TPB, TPB>>>();
    k_fill<<<(EE + TPB - 1) / TPB, TPB>>>(ei);

    // ---- side stream: gemm1 (needs Wh + dinv), overlaps scan/fill
    cudaStreamWaitEvent(s1, evDinv, 0);
    k_gemm_tc<true><<<GEMM_BLOCKS, 256, GEMM_SMEM, s1>>>(x, Wh, t);
    cudaEventRecord(evG1, s1);

    // ---- join, then layer 1 aggregation onward (serial on main stream)
    cudaStreamWaitEvent(0, evG1, 0);
    k_agg16<false><<<AGG_BLOCKS, TPB>>>(beta, nullptr, nullptr);
    // ---- layer 2
    k_gemm_tc<false><<<GEMM_BLOCKS, 256, GEMM_SMEM>>>(h, Wh + HH * HH, t);
    k_agg16<false><<<AGG_BLOCKS, TPB>>>(beta + HH, nullptr, nullptr);
    // ---- layer 3 (fused mean-pool + linear head via per-node dot)
    k_gemm_tc<false><<<GEMM_BLOCKS, 256, GEMM_SMEM>>>(h, Wh + 2 * HH * HH, t);
    k_agg16<true><<<AGG_BLOCKS, TPB>>>(beta + 2 * HH, Wl, batch);

    k_final<<<(GG + TPB - 1) / TPB, TPB>>>((float*)d_out, bl);
}